// round 15
// baseline (speedup 1.0000x reference)
#include <cuda_runtime.h>
#include <cuda_bf16.h>
#include <cuda_fp16.h>
#include <cstdint>

#define DI __device__ __forceinline__

// ---------------- problem sizes ----------------
constexpr int Bc = 32, Sc = 256, Tc = 64, T1c = 65;
constexpr int Hc = 512, Ec = 300, Vc = 32000, H3c = 1536;
constexpr int ROWS = Bc * Tc;            // 2048
constexpr int EP = 320;                  // padded embed K

// ---------------- fp32 scratch ----------------
__device__ __align__(16) float g_gi   [ROWS * H3c];
__device__ __align__(16) float g_hta  [Hc * Bc];
__device__ __align__(16) float g_htb  [Hc * Bc];
__device__ __align__(16) float g_scores[ROWS * Sc];
__device__ int g_bar_ctr;
__device__ unsigned int g_bar_gen;

// ---------------- bf16 hi/lo planes (gi path only) ----------------
#define PLANES_DECL(name, n) \
    __device__ __align__(16) __nv_bfloat16 name##_hi[n]; \
    __device__ __align__(16) __nv_bfloat16 name##_lo[n];

PLANES_DECL(g_x,     ROWS * EP)
PLANES_DECL(g_wih0,  H3c * EP)
PLANES_DECL(g_wih1,  H3c * Hc)
PLANES_DECL(g_hs0,   ROWS * Hc)

// ---------------- fp16 planes ----------------
__device__ __align__(16) __half g_enc_fh[Bc * Sc * 2 * Hc];
__device__ __align__(16) __half g_enc_fl[Bc * Sc * 2 * Hc];
__device__ __align__(16) __half g_attnW_f[Hc * 2 * Hc];
__device__ __align__(16) __half g_proj_f[Bc * Sc * Hc];
__device__ __align__(16) __half g_encT_f[Bc * 2 * Hc * Sc];
__device__ __align__(16) __half g_attn_fh[ROWS * Sc];
__device__ __align__(16) __half g_attn_fl[ROWS * Sc];
__device__ __align__(16) __half g_cat_fh[ROWS * H3c];
__device__ __align__(16) __half g_cat_fl[ROWS * H3c];
__device__ __align__(16) __half g_awW_f[H3c * H3c];
__device__ __align__(16) __half g_o_f  [ROWS * H3c];
__device__ __align__(16) __half g_outW_f[(long long)Vc * H3c];

// ---------------- helpers ----------------
DI void mma16(float c[4], const uint32_t a[4], const uint32_t b[2]) {
    asm volatile(
        "mma.sync.aligned.m16n8k16.row.col.f32.bf16.bf16.f32 "
        "{%0,%1,%2,%3}, {%4,%5,%6,%7}, {%8,%9}, {%0,%1,%2,%3};"
        : "+f"(c[0]), "+f"(c[1]), "+f"(c[2]), "+f"(c[3])
        : "r"(a[0]), "r"(a[1]), "r"(a[2]), "r"(a[3]), "r"(b[0]), "r"(b[1]));
}
DI void mma16h(float c[4], const uint32_t a[4], const uint32_t b[2]) {
    asm volatile(
        "mma.sync.aligned.m16n8k16.row.col.f32.f16.f16.f32 "
        "{%0,%1,%2,%3}, {%4,%5,%6,%7}, {%8,%9}, {%0,%1,%2,%3};"
        : "+f"(c[0]), "+f"(c[1]), "+f"(c[2]), "+f"(c[3])
        : "r"(a[0]), "r"(a[1]), "r"(a[2]), "r"(a[3]), "r"(b[0]), "r"(b[1]));
}
#define LDSM4(R, addr) \
    asm volatile("ldmatrix.sync.aligned.m8n8.x4.shared.b16 {%0,%1,%2,%3}, [%4];" \
                 : "=r"((R)[0]), "=r"((R)[1]), "=r"((R)[2]), "=r"((R)[3]) : "r"(addr))

DI void cpa16(uint32_t dst, const void* src, bool ok) {
    int sz = ok ? 16 : 0;
    asm volatile("cp.async.cg.shared.global [%0], [%1], 16, %2;\n"
                 :: "r"(dst), "l"(src), "r"(sz));
}
DI void cpa16u(uint32_t dst, const void* src) {
    asm volatile("cp.async.cg.shared.global [%0], [%1], 16;\n"
                 :: "r"(dst), "l"(src));
}
DI void cp_commit() { asm volatile("cp.async.commit_group;\n"); }
DI void cp_wait2()  { asm volatile("cp.async.wait_group 2;\n"); }
DI void cp_wait1()  { asm volatile("cp.async.wait_group 1;\n"); }
DI void cp_wait0()  { asm volatile("cp.async.wait_group 0;\n"); }

DI void splits(float v, __nv_bfloat16& h, __nv_bfloat16& l) {
    h = __float2bfloat16(v);
    l = __float2bfloat16(v - __bfloat162float(h));
}
DI void splith(float v, __half& h, __half& l) {
    h = __float2half_rn(v);
    l = __float2half_rn(v - __half2float(h));
}

// ---------------- split kernels ----------------
__global__ void split_kernel(const float* __restrict__ s,
                             __nv_bfloat16* __restrict__ hi,
                             __nv_bfloat16* __restrict__ lo, int n4) {
    int i = blockIdx.x * blockDim.x + threadIdx.x;
    if (i >= n4) return;
    float4 v = ((const float4*)s)[i];
    __nv_bfloat162 h0 = __floats2bfloat162_rn(v.x, v.y);
    __nv_bfloat162 h1 = __floats2bfloat162_rn(v.z, v.w);
    __nv_bfloat162 l0 = __floats2bfloat162_rn(v.x - __bfloat162float(__low2bfloat16(h0)),
                                              v.y - __bfloat162float(__high2bfloat16(h0)));
    __nv_bfloat162 l1 = __floats2bfloat162_rn(v.z - __bfloat162float(__low2bfloat16(h1)),
                                              v.w - __bfloat162float(__high2bfloat16(h1)));
    ((__nv_bfloat162*)hi)[2 * i] = h0;
    ((__nv_bfloat162*)hi)[2 * i + 1] = h1;
    ((__nv_bfloat162*)lo)[2 * i] = l0;
    ((__nv_bfloat162*)lo)[2 * i + 1] = l1;
}

__global__ void split_pad_kernel(const float* __restrict__ s,
                                 __nv_bfloat16* __restrict__ hi,
                                 __nv_bfloat16* __restrict__ lo,
                                 int N, int K, int Kp) {
    int i = blockIdx.x * blockDim.x + threadIdx.x;
    int total = N * Kp;
    if (i >= total) return;
    int row = i / Kp, col = i % Kp;
    float v = (col < K) ? s[(long long)row * K + col] : 0.f;
    __nv_bfloat16 h, l; splits(v, h, l);
    hi[i] = h; lo[i] = l;
}

__global__ void split_half_kernel(const float* __restrict__ s,
                                  __half* __restrict__ h, int n4) {
    int i = blockIdx.x * blockDim.x + threadIdx.x;
    if (i >= n4) return;
    float4 v = ((const float4*)s)[i];
    ((__half2*)h)[2 * i]     = __floats2half2_rn(v.x, v.y);
    ((__half2*)h)[2 * i + 1] = __floats2half2_rn(v.z, v.w);
}

__global__ void split_half2_kernel(const float* __restrict__ s,
                                   __half* __restrict__ hi,
                                   __half* __restrict__ lo, int n4) {
    int i = blockIdx.x * blockDim.x + threadIdx.x;
    if (i >= n4) return;
    float4 v = ((const float4*)s)[i];
    __half2 h0 = __floats2half2_rn(v.x, v.y);
    __half2 h1 = __floats2half2_rn(v.z, v.w);
    __half2 l0 = __floats2half2_rn(v.x - __half2float(__low2half(h0)),
                                   v.y - __half2float(__high2half(h0)));
    __half2 l1 = __floats2half2_rn(v.z - __half2float(__low2half(h1)),
                                   v.w - __half2float(__high2half(h1)));
    ((__half2*)hi)[2 * i] = h0; ((__half2*)hi)[2 * i + 1] = h1;
    ((__half2*)lo)[2 * i] = l0; ((__half2*)lo)[2 * i + 1] = l1;
}

// ---------------- embed gather + relu -> padded bf16 planes ----------------
__global__ void embed_relu_kernel(const int* __restrict__ words,
                                  const float* __restrict__ embed) {
    int row = blockIdx.x;
    int b = row >> 6, t = row & 63;
    int w = words[b * T1c + t];
    const float* e = embed + (long long)w * Ec;
    for (int i = threadIdx.x; i < EP; i += blockDim.x) {
        float v = (i < Ec) ? fmaxf(e[i], 0.f) : 0.f;
        __nv_bfloat16 h, l; splits(v, h, l);
        g_x_hi[(long long)row * EP + i] = h;
        g_x_lo[(long long)row * EP + i] = l;
    }
}

// ---------------- h0 (transposed) ----------------
__global__ void h0t_kernel(const float* __restrict__ ehid, int layer) {
    int i = blockIdx.x * blockDim.x + threadIdx.x;
    if (i < Bc * Hc) {
        int b = i >> 9, j = i & 511;
        g_hta[j * Bc + b] = ehid[layer * Bc * Hc + i] + ehid[(layer + 2) * Bc * Hc + i];
    }
}

// ------------- encoder transpose [b][s][d] -> [b][d][s] fp16 -------------
__global__ void transpose_enc(const float* __restrict__ enc) {
    __shared__ float t[32][33];
    int b = blockIdx.z;
    int d0 = blockIdx.x * 32, s0 = blockIdx.y * 32;
    int tx = threadIdx.x, ty = threadIdx.y;
#pragma unroll
    for (int i = 0; i < 4; i++)
        t[ty + 8 * i][tx] =
            enc[((long long)b * Sc + s0 + ty + 8 * i) * (2 * Hc) + d0 + tx];
    __syncthreads();
#pragma unroll
    for (int i = 0; i < 4; i++) {
        float v = t[tx][ty + 8 * i];
        long long idx = ((long long)b * (2 * Hc) + d0 + ty + 8 * i) * Sc + s0 + tx;
        g_encT_f[idx] = __float2half_rn(v);
    }
}

// ---------------- persistent GRU layer ----------------
// dyn smem: ws[6144] + hs[16384] floats = 90112 B
__global__ void __launch_bounds__(256, 1)
gru_layer_kernel(const float* __restrict__ Whh, const float* __restrict__ bhh,
                 int layer) {
    extern __shared__ float dsm[];
    float* ws = dsm;            // 6144 floats
    float* hs = dsm + 6144;     // 16384 floats [k][b]
    __shared__ float sp[3][4][32];
    int tid = threadIdx.x, bid = blockIdx.x;
    int b = tid & 31, jl = (tid >> 5) & 3, kh = tid >> 7;
    int j = bid * 4 + jl;
    uint32_t hsu = (uint32_t)__cvta_generic_to_shared(hs);

    for (int i = tid; i < 6144; i += 256) {
        int g = i >> 11, r = (i >> 9) & 3, k = i & 511;
        ws[i] = Whh[(long long)(g * Hc + bid * 4 + r) * Hc + k];
    }
    float br = bhh[j], bz = bhh[j + Hc], bn = bhh[j + 2 * Hc];
    __syncthreads();
    const float* wr = &ws[jl * 512];
    const float* wz = &ws[2048 + jl * 512];
    const float* wn = &ws[4096 + jl * 512];

    for (int t = 0; t < Tc; t++) {
        const float* hin = (t & 1) ? g_htb : g_hta;
        float* hout      = (t & 1) ? g_hta : g_htb;
#pragma unroll
        for (int g = 0; g < 4; g++) {
            for (int i = tid; i < 1024; i += 256) {
                int idx = g * 1024 + i;
                cpa16u(hsu + idx * 16, hin + idx * 4);
            }
            cp_commit();
        }

        float ar = 0.f, az = 0.f, an = 0.f;
        cp_wait2();
        __syncthreads();
        int kA = kh * 128;
#pragma unroll 4
        for (int k = kA; k < kA + 128; k += 4) {
            float4 r4 = *(const float4*)(wr + k);
            float4 z4 = *(const float4*)(wz + k);
            float4 n4 = *(const float4*)(wn + k);
            float h0v = hs[(k + 0) * Bc + b];
            float h1v = hs[(k + 1) * Bc + b];
            float h2v = hs[(k + 2) * Bc + b];
            float h3v = hs[(k + 3) * Bc + b];
            ar += r4.x * h0v + r4.y * h1v + r4.z * h2v + r4.w * h3v;
            az += z4.x * h0v + z4.y * h1v + z4.z * h2v + z4.w * h3v;
            an += n4.x * h0v + n4.y * h1v + n4.z * h2v + n4.w * h3v;
        }
        cp_wait0();
        __syncthreads();
        int kB = 256 + kh * 128;
#pragma unroll 4
        for (int k = kB; k < kB + 128; k += 4) {
            float4 r4 = *(const float4*)(wr + k);
            float4 z4 = *(const float4*)(wz + k);
            float4 n4 = *(const float4*)(wn + k);
            float h0v = hs[(k + 0) * Bc + b];
            float h1v = hs[(k + 1) * Bc + b];
            float h2v = hs[(k + 2) * Bc + b];
            float h3v = hs[(k + 3) * Bc + b];
            ar += r4.x * h0v + r4.y * h1v + r4.z * h2v + r4.w * h3v;
            az += z4.x * h0v + z4.y * h1v + z4.z * h2v + z4.w * h3v;
            an += n4.x * h0v + n4.y * h1v + n4.z * h2v + n4.w * h3v;
        }
        if (kh) { sp[0][jl][b] = ar; sp[1][jl][b] = az; sp[2][jl][b] = an; }
        __syncthreads();
        if (!kh) {
            ar += sp[0][jl][b]; az += sp[1][jl][b]; an += sp[2][jl][b];
            int row = b * Tc + t;
            const float* g = g_gi + (long long)row * H3c;
            float r = 1.f / (1.f + expf(-(g[j] + ar + br)));
            float z = 1.f / (1.f + expf(-(g[j + Hc] + az + bz)));
            float n = tanhf(g[j + 2 * Hc] + r * (an + bn));
            float hold = hs[j * Bc + b];
            float hnew = (1.f - z) * n + z * hold;
            __stcg(hout + j * Bc + b, hnew);
            if (layer == 0) {
                __nv_bfloat16 h, l; splits(hnew, h, l);
                g_hs0_hi[(long long)row * Hc + j] = h;
                g_hs0_lo[(long long)row * Hc + j] = l;
            } else {
                __half h, l; splith(hnew, h, l);
                g_cat_fh[(long long)row * H3c + j] = h;
                g_cat_fl[(long long)row * H3c + j] = l;
            }
        }
        __syncthreads();
        __threadfence();
        if (tid == 0) {
            unsigned int gen = atomicAdd(&g_bar_gen, 0u);
            int old = atomicAdd(&g_bar_ctr, 1);
            if (old == (int)gridDim.x - 1) {
                atomicExch(&g_bar_ctr, 0);
                __threadfence();
                atomicAdd(&g_bar_gen, 1u);
            } else {
                while (atomicAdd(&g_bar_gen, 0u) == gen) {}
            }
        }
        __syncthreads();
    }
}

// ---------------- softmax (256 wide) -> attn fp16 planes ----------------
__global__ void softmax_kernel() {
    int row = blockIdx.x, tid = threadIdx.x;
    __shared__ float sm_[8], ss_[8];
    float v = g_scores[(long long)row * Sc + tid];
    float m = v;
#pragma unroll
    for (int o = 16; o; o >>= 1) m = fmaxf(m, __shfl_xor_sync(~0u, m, o));
    if ((tid & 31) == 0) sm_[tid >> 5] = m;
    __syncthreads();
    float mm = sm_[0];
#pragma unroll
    for (int i = 1; i < 8; i++) mm = fmaxf(mm, sm_[i]);
    float e = expf(v - mm);
    float s = e;
#pragma unroll
    for (int o = 16; o; o >>= 1) s += __shfl_xor_sync(~0u, s, o);
    if ((tid & 31) == 0) ss_[tid >> 5] = s;
    __syncthreads();
    float tot = 0.f;
#pragma unroll
    for (int i = 0; i < 8; i++) tot += ss_[i];
    float p = e / tot;
    __half h, l; splith(p, h, l);
    g_attn_fh[(long long)row * Sc + tid] = h;
    g_attn_fl[(long long)row * Sc + tid] = l;
}

// ======================= bf16x3 pipelined tensor GEMM (gi only) ==============
constexpr int GSTAGE = 32768;
constexpr int GSMEM  = 3 * GSTAGE;

__global__ void __launch_bounds__(256, 1)
bfx3_gemm(const __nv_bfloat16* __restrict__ Ahi, const __nv_bfloat16* __restrict__ Alo,
          const __nv_bfloat16* __restrict__ Bhi, const __nv_bfloat16* __restrict__ Blo,
          const float* __restrict__ bias, float* __restrict__ C,
          int M, int N, int K, int lda, int ldc) {
    extern __shared__ char smem[];
    uint32_t su = (uint32_t)__cvta_generic_to_shared(smem);

    const int m0 = blockIdx.x * 128, n0 = blockIdx.y * 128;
    const int tid = threadIdx.x;
    const int lane = tid & 31, wid = tid >> 5;
    const int wm = wid & 1, wn = wid >> 1;
    const int lr = lane >> 2, lc = lane & 3;

    float c[4][4][4] = {};

    auto issue_load = [&](int stage, int kt) {
        int kb = kt * 32;
        uint32_t sb = su + stage * GSTAGE;
#pragma unroll
        for (int i = 0; i < 8; i++) {
            int chunkid = tid + 256 * i;
            int plane = chunkid >> 9;
            int w = chunkid & 511;
            int r = w >> 2, cck = w & 3;
            uint32_t dst = sb + plane * 8192 + r * 64 + ((cck ^ ((r >> 1) & 3)) << 4);
            const __nv_bfloat16* src;
            if (plane < 2)
                src = (plane == 0 ? Ahi : Alo) + (long long)(m0 + r) * lda + kb + cck * 8;
            else
                src = (plane == 2 ? Bhi : Blo) + (long long)(n0 + r) * K + kb + cck * 8;
            cpa16u(dst, src);
        }
    };

    const int kt_count = K >> 5;
    issue_load(0, 0); cp_commit();
    issue_load(1, 1); cp_commit();

    for (int kt = 0; kt < kt_count; kt++) {
        if (kt + 2 < kt_count) cp_wait1(); else cp_wait0();
        __syncthreads();
        if (kt + 2 < kt_count) { issue_load((kt + 2) % 3, kt + 2); cp_commit(); }

        uint32_t sb = su + (kt % 3) * GSTAGE;
#pragma unroll
        for (int ks = 0; ks < 2; ks++) {
            uint32_t ah[4][4], al[4][4], bh[2][4], bl[2][4];
#pragma unroll
            for (int mi = 0; mi < 4; mi++) {
                int row = wm * 64 + mi * 16 + (lane & 15);
                int ch = 2 * ks + (lane >> 4);
                uint32_t a = sb + row * 64 + ((ch ^ ((row >> 1) & 3)) << 4);
                LDSM4(ah[mi], a);
                LDSM4(al[mi], a + 8192);
            }
#pragma unroll
            for (int np = 0; np < 2; np++) {
                int row = wn * 32 + np * 16 + ((lane >> 4) << 3) + (lane & 7);
                int ch = 2 * ks + ((lane >> 3) & 1);
                uint32_t a = sb + 16384 + row * 64 + ((ch ^ ((row >> 1) & 3)) << 4);
                LDSM4(bh[np], a);
                LDSM4(bl[np], a + 8192);
            }
#pragma unroll
            for (int mi = 0; mi < 4; mi++)
#pragma unroll
                for (int ni = 0; ni < 4; ni++)
                    mma16(c[mi][ni], ah[mi], &bh[ni >> 1][(ni & 1) * 2]);
#pragma unroll
            for (int mi = 0; mi < 4; mi++)
#pragma unroll
                for (int ni = 0; ni < 4; ni++)
                    mma16(c[mi][ni], ah[mi], &bl[ni >> 1][(ni & 1) * 2]);
#pragma unroll
            for (int mi = 0; mi < 4; mi++)
#pragma unroll
                for (int ni = 0; ni < 4; ni++)
                    mma16(c[mi][ni], al[mi], &bh[ni >> 1][(ni & 1) * 2]);
        }
        __syncthreads();
    }

#pragma unroll
    for (int mi = 0; mi < 4; mi++) {
#pragma unroll
        for (int ni = 0; ni < 4; ni++) {
            int row = m0 + wm * 64 + mi * 16 + lr;
            int col = n0 + wn * 32 + ni * 8 + lc * 2;
            float b0 = bias[col], b1 = bias[col + 1];
            *(float2*)(C + (long long)row * ldc + col) =
                make_float2(c[mi][ni][0] + b0, c[mi][ni][1] + b1);
            *(float2*)(C + (long long)(row + 8) * ldc + col) =
                make_float2(c[mi][ni][2] + b0, c[mi][ni][3] + b1);
        }
    }
}

// ============ fp16 pipelined GEMM: C = (sum A-terms) @ Bf^T (+bias) ============
constexpr int FPL = 8192;

template <int AT, int OUT, bool RELU, bool GUARD>
__global__ void __launch_bounds__(256, 2)
fph_gemm(const __half* __restrict__ Ahi, const __half* __restrict__ Alo,
         const __half* __restrict__ Bf, const float* __restrict__ bias,
         float* __restrict__ C, __half* __restrict__ Ch, __half* __restrict__ Cl,
         int M, int N, int K, int lda, int ldc,
         long long sA, long long sB, long long sC) {
    extern __shared__ char smem[];
    uint32_t su = (uint32_t)__cvta_generic_to_shared(smem);
    constexpr int NPL = AT + 1;
    constexpr int STG = NPL * FPL;

    Ahi += (long long)blockIdx.z * sA;
    if (AT == 2) Alo += (long long)blockIdx.z * sA;
    Bf += (long long)blockIdx.z * sB;

    const int m0 = blockIdx.x * 128, n0 = blockIdx.y * 128;
    const int tid = threadIdx.x;
    const int lane = tid & 31, wid = tid >> 5;
    const int wm = wid & 1, wn = wid >> 1;
    const int lr = lane >> 2, lc = lane & 3;

    float c[4][4][4] = {};

    auto issue_load = [&](int stage, int kt) {
        int kb = kt * 32;
        uint32_t sb = su + stage * STG;
#pragma unroll
        for (int i = 0; i < NPL * 2; i++) {
            int chunkid = tid + 256 * i;
            int plane = chunkid >> 9;
            int w = chunkid & 511;
            int r = w >> 2, cck = w & 3;
            uint32_t dst = sb + plane * FPL + r * 64 + ((cck ^ ((r >> 1) & 3)) << 4);
            const __half* src;
            bool ok = true;
            if (plane < AT) {
                src = (plane == 0 ? Ahi : Alo) + (long long)(m0 + r) * lda + kb + cck * 8;
                if (GUARD) ok = (m0 + r) < M;
            } else {
                src = Bf + (long long)(n0 + r) * K + kb + cck * 8;
            }
            if (GUARD) cpa16(dst, src, ok); else cpa16u(dst, src);
        }
    };

    const int kt_count = K >> 5;
    issue_load(0, 0); cp_commit();
    issue_load(1, 1); cp_commit();

    for (int kt = 0; kt < kt_count; kt++) {
        if (kt + 2 < kt_count) cp_wait1(); else cp_wait0();
        __syncthreads();
        if (kt + 2 < kt_count) { issue_load((kt + 2) % 3, kt + 2); cp_commit(); }

        uint32_t sb = su + (kt % 3) * STG;
#pragma unroll
        for (int ks = 0; ks < 2; ks++) {
            uint32_t ah[AT][4][4], bh[2][4];
#pragma unroll
            for (int t = 0; t < AT; t++)
#pragma unroll
                for (int mi = 0; mi < 4; mi++) {
                    int row = wm * 64 + mi * 16 + (lane & 15);
                    int ch = 2 * ks + (lane >> 4);
                    uint32_t a = sb + t * FPL + row * 64 + ((ch ^ ((row >> 1) & 3)) << 4);
                    LDSM4(ah[t][mi], a);
                }
#pragma unroll
            for (int np = 0; np < 2; np++) {
                int row = wn * 32 + np * 16 + ((lane >> 4) << 3) + (lane & 7);
                int ch = 2 * ks + ((lane >> 3) & 1);
                uint32_t a = sb + AT * FPL + row * 64 + ((ch ^ ((row >> 1) & 3)) << 4);
                LDSM4(bh[np], a);
            }
#pragma unroll
            for (int t = 0; t < AT; t++)
#pragma unroll
                for (int mi = 0; mi < 4; mi++)
#pragma unroll
                    for (int ni = 0; ni < 4; ni++)
                        mma16h(c[mi][ni], ah[t][mi], &bh[ni >> 1][(ni & 1) * 2]);
        }
        __syncthreads();
    }

#pragma unroll
    for (int mi = 0; mi < 4; mi++) {
#pragma unroll
        for (int ni = 0; ni < 4; ni++) {
            int row = m0 + wm * 64 + mi * 16 + lr;
            int col = n0 + wn * 32 + ni * 8 + lc * 2;
            float b0 = bias ? bias[col] : 0.f;
            float b1 = bias ? bias[col + 1] : 0.f;
            float v0 = c[mi][ni][0] + b0, v1 = c[mi][ni][1] + b1;
            float v2 = c[mi][ni][2] + b0, v3 = c[mi][ni][3] + b1;
            if (RELU) {
                v0 = fmaxf(v0, 0.f); v1 = fmaxf(v1, 0.f);
                v2 = fmaxf(v2, 0.f); v3 = fmaxf(v3, 0.f);
            }
            bool ok0 = !GUARD || row < M;
            bool ok1 = !GUARD || (row + 8) < M;
            if (OUT == 0) {
                float* Cz = C + (long long)blockIdx.z * sC;
                if (ok0)
                    *(float2*)(Cz + (long long)row * ldc + col) = make_float2(v0, v1);
                if (ok1)
                    *(float2*)(Cz + (long long)(row + 8) * ldc + col) = make_float2(v2, v3);
            } else if (OUT == 1) {
                __half* Co = Ch + (long long)blockIdx.z * sC;
                if (ok0)
                    *(__half2*)(Co + (long long)row * ldc + col) = __floats2half2_rn(v0, v1);
                if (ok1)
                    *(__half2*)(Co + (long long)(row + 8) * ldc + col) = __floats2half2_rn(v2, v3);
            } else {
                __half* Coh = Ch + (long long)blockIdx.z * sC;
                __half* Col = Cl + (long long)blockIdx.z * sC;
                if (ok0) {
                    __half2 h = __floats2half2_rn(v0, v1);
                    __half2 l = __floats2half2_rn(v0 - __half2float(__low2half(h)),
                                                  v1 - __half2float(__high2half(h)));
                    *(__half2*)(Coh + (long long)row * ldc + col) = h;
                    *(__half2*)(Col + (long long)row * ldc + col) = l;
                }
                if (ok1) {
                    __half2 h = __floats2half2_rn(v2, v3);
                    __half2 l = __floats2half2_rn(v2 - __half2float(__low2half(h)),
                                                  v3 - __half2float(__high2half(h)));
                    *(__half2*)(Coh + (long long)(row + 8) * ldc + col) = h;
                    *(__half2*)(Col + (long long)(row + 8) * ldc + col) = l;
                }
            }
        }
    }
}

// ====== persistent fp16 logits GEMM: 4-stage, 1 sync/iter, tile loop ======
constexpr int LSTG  = 2 * FPL;         // 16 KB per stage (A + B planes)
constexpr int LSMEM = 4 * LSTG;        // 64 KB

__global__ void __launch_bounds__(256, 2)
fph_logits(const __half* __restrict__ Af, const __half* __restrict__ Bf,
           const float* __restrict__ bias, float* __restrict__ C,
           int M, int N, int K, int lda, int ldc) {
    extern __shared__ char smem[];
    uint32_t su = (uint32_t)__cvta_generic_to_shared(smem);
    const int tid = threadIdx.x;
    const int lane = tid & 31, wid = tid >> 5;
    const int wm = wid & 1, wn = wid >> 1;
    const int lr = lane >> 2, lc = lane & 3;
    const int mt = M >> 7;
    const int tiles = (N >> 7) * mt;
    const int ktc = K >> 5;

    for (int tile = blockIdx.x; tile < tiles; tile += gridDim.x) {
        const int m0 = (tile % mt) << 7;
        const int n0 = (tile / mt) << 7;

        auto issue_load = [&](int stage, int kt) {
            int kb = kt * 32;
            uint32_t sb = su + stage * LSTG;
#pragma unroll
            for (int i = 0; i < 4; i++) {
                int chunkid = tid + 256 * i;
                int plane = chunkid >> 9;
                int w = chunkid & 511;
                int r = w >> 2, cck = w & 3;
                uint32_t dst = sb + plane * FPL + r * 64 + ((cck ^ ((r >> 1) & 3)) << 4);
                const __half* src = (plane == 0)
                    ? Af + (long long)(m0 + r) * lda + kb + cck * 8
                    : Bf + (long long)(n0 + r) * K + kb + cck * 8;
                cpa16u(dst, src);
            }
        };

        float c[4][4][4] = {};
        issue_load(0, 0); cp_commit();
        issue_load(1, 1); cp_commit();
        issue_load(2, 2); cp_commit();

        for (int kt = 0; kt < ktc; kt++) {
            cp_wait2();
            __syncthreads();
            if (kt + 3 < ktc) issue_load((kt + 3) & 3, kt + 3);
            cp_commit();                       // uniform group count (may be empty)

            uint32_t sb = su + (kt & 3) * LSTG;
#pragma unroll
            for (int ks = 0; ks < 2; ks++) {
                uint32_t ah[4][4], bh[2][4];
#pragma unroll
                for (int mi = 0; mi < 4; mi++) {
                    int row = wm * 64 + mi * 16 + (lane & 15);
                    int ch = 2 * ks + (lane >> 4);
                    uint32_t a = sb + row * 64 + ((ch ^ ((row >> 1) & 3)) << 4);
                    LDSM4(ah[mi], a);
                }
#pragma unroll
                for (int np = 0; np < 2; np++) {
                    int row = wn * 32 + np * 16 + ((lane >> 4) << 3) + (lane & 7);
                    int ch = 2 * ks + ((lane >> 3) & 1);
                    uint32_t a = sb + FPL + row * 64 + ((ch ^ ((row >> 1) & 3)) << 4);
                    LDSM4(bh[np], a);
                }
#pragma unroll
                for (int mi = 0; mi < 4; mi++)
#pragma unroll
                    for (int ni = 0; ni < 4; ni++)
                        mma16h(c[mi][ni], ah[mi], &bh[ni >> 1][(ni & 1) * 2]);
            }
        }

#pragma unroll
        for (int mi = 0; mi < 4; mi++) {
#pragma unroll
            for (int ni = 0; ni < 4; ni++) {
                int row = m0 + wm * 64 + mi * 16 + lr;
                int col = n0 + wn * 32 + ni * 8 + lc * 2;
                float b0 = bias[col], b1 = bias[col + 1];
                *(float2*)(C + (long long)row * ldc + col) =
                    make_float2(c[mi][ni][0] + b0, c[mi][ni][1] + b1);
                *(float2*)(C + (long long)(row + 8) * ldc + col) =
                    make_float2(c[mi][ni][2] + b0, c[mi][ni][3] + b1);
            }
        }
        __syncthreads();   // stage reuse across tiles
    }
}

// ---------------- host launch ----------------
extern "C" void kernel_launch(void* const* d_in, const int* in_sizes, int n_in,
                              void* d_out, int out_size) {
    (void)in_sizes; (void)n_in; (void)out_size;
    const float* enc    = (const float*)d_in[0];
    const float* ehid   = (const float*)d_in[1];
    const int*   words  = (const int*)d_in[2];
    const float* embed  = (const float*)d_in[3];
    const float* Wih0   = (const float*)d_in[4];
    const float* Whh0   = (const float*)d_in[5];
    const float* bih0   = (const float*)d_in[6];
    const float* bhh0   = (const float*)d_in[7];
    const float* Wih1   = (const float*)d_in[8];
    const float* Whh1   = (const float*)d_in[9];
    const float* bih1   = (const float*)d_in[10];
    const float* bhh1   = (const float*)d_in[11];
    const float* attn_W = (const float*)d_in[12];
    const float* attn_b = (const float*)d_in[13];
    const float* aw_W   = (const float*)d_in[14];
    const float* aw_b   = (const float*)d_in[15];
    const float* out_W  = (const float*)d_in[16];
    const float* out_b  = (const float*)d_in[17];
    float* out = (float*)d_out;

    float *p_gi, *p_sc;
    cudaGetSymbolAddress((void**)&p_gi, g_gi);
    cudaGetSymbolAddress((void**)&p_sc, g_scores);

#define GETP(sym) \
    __nv_bfloat16 *sym##_h, *sym##_l; \
    cudaGetSymbolAddress((void**)&sym##_h, sym##_hi); \
    cudaGetSymbolAddress((void**)&sym##_l, sym##_lo);
    GETP(g_x) GETP(g_wih0) GETP(g_wih1) GETP(g_hs0)
#undef GETP
    __half *p_encfh, *p_encfl, *p_awnf, *p_projf, *p_encTf;
    __half *p_attnfh, *p_attnfl, *p_catfh, *p_catfl, *p_awWf, *p_of, *p_wf;
    cudaGetSymbolAddress((void**)&p_encfh,  g_enc_fh);
    cudaGetSymbolAddress((void**)&p_encfl,  g_enc_fl);
    cudaGetSymbolAddress((void**)&p_awnf,   g_attnW_f);
    cudaGetSymbolAddress((void**)&p_projf,  g_proj_f);
    cudaGetSymbolAddress((void**)&p_encTf,  g_encT_f);
    cudaGetSymbolAddress((void**)&p_attnfh, g_attn_fh);
    cudaGetSymbolAddress((void**)&p_attnfl, g_attn_fl);
    cudaGetSymbolAddress((void**)&p_catfh,  g_cat_fh);
    cudaGetSymbolAddress((void**)&p_catfl,  g_cat_fl);
    cudaGetSymbolAddress((void**)&p_awWf,   g_awW_f);
    cudaGetSymbolAddress((void**)&p_of,     g_o_f);
    cudaGetSymbolAddress((void**)&p_wf,     g_outW_f);

    cudaFuncSetAttribute(bfx3_gemm,
                         cudaFuncAttributeMaxDynamicSharedMemorySize, GSMEM);
    cudaFuncSetAttribute((fph_gemm<2, 1, false, false>),
                         cudaFuncAttributeMaxDynamicSharedMemorySize, 3 * 3 * FPL);
    cudaFuncSetAttribute((fph_gemm<2, 0, false, true>),
                         cudaFuncAttributeMaxDynamicSharedMemorySize, 3 * 3 * FPL);
    cudaFuncSetAttribute((fph_gemm<2, 2, false, true>),
                         cudaFuncAttributeMaxDynamicSharedMemorySize, 3 * 3 * FPL);
    cudaFuncSetAttribute((fph_gemm<2, 1, true, false>),
                         cudaFuncAttributeMaxDynamicSharedMemorySize, 3 * 3 * FPL);
    cudaFuncSetAttribute(fph_logits,
                         cudaFuncAttributeMaxDynamicSharedMemorySize, LSMEM);
    cudaFuncSetAttribute(gru_layer_kernel,
                         cudaFuncAttributeMaxDynamicSharedMemorySize, 90112);

    // ---- streams/events (frozen round-10 structure) ----
    static cudaStream_t s1 = nullptr, s2 = nullptr;
    static cudaEvent_t e0 = nullptr, e_aw = nullptr, e_outw = nullptr, e_proj = nullptr;
    if (!s1) {
        cudaStreamCreateWithFlags(&s1, cudaStreamNonBlocking);
        cudaStreamCreateWithFlags(&s2, cudaStreamNonBlocking);
        cudaEventCreateWithFlags(&e0,     cudaEventDisableTiming);
        cudaEventCreateWithFlags(&e_aw,   cudaEventDisableTiming);
        cudaEventCreateWithFlags(&e_outw, cudaEventDisableTiming);
        cudaEventCreateWithFlags(&e_proj, cudaEventDisableTiming);
    }

    // fork
    cudaEventRecord(e0, 0);
    cudaStreamWaitEvent(s1, e0, 0);
    cudaStreamWaitEvent(s2, e0, 0);

    // ---- s1: weight conversions for the output head ----
    {
        int n4 = H3c * H3c / 4;
        split_half_kernel<<<(n4 + 255) / 256, 256, 0, s1>>>(aw_W, p_awWf, n4);
        cudaEventRecord(e_aw, s1);
        n4 = Vc * H3c / 4;
        split_half_kernel<<<(n4 + 255) / 256, 256, 0, s1>>>(out_W, p_wf, n4);
        cudaEventRecord(e_outw, s1);
    }

    // ---- s2: attention prep + proj GEMM ----
    {
        int n4 = Bc * Sc * 2 * Hc / 4;
        split_half2_kernel<<<(n4 + 255) / 256, 256, 0, s2>>>(enc, p_encfh, p_encfl, n4);
        n4 = Hc * 2 * Hc / 4;
        split_half_kernel<<<(n4 + 255) / 256, 256, 0, s2>>>(attn_W, p_awnf, n4);
        transpose_enc<<<dim3(32, 8, 32), dim3(32, 8), 0, s2>>>(enc);
        fph_gemm<2, 1, false, false><<<dim3(64, 4), 256, 3 * 3 * FPL, s2>>>(
            p_encfh, p_encfl, p_awnf, attn_b, nullptr, p_projf, nullptr,
            Bc * Sc, Hc, 2 * Hc, 2 * Hc, Hc, 0, 0, 0);
        cudaEventRecord(e_proj, s2);
    }

    // ---- main stream: GRU critical path ----
    {
        int tot = H3c * EP;
        split_pad_kernel<<<(tot + 255) / 256, 256>>>(Wih0, g_wih0_h, g_wih0_l,
                                                     H3c, Ec, EP);
        int n4 = H3c * Hc / 4;
        split_kernel<<<(n4 + 255) / 256, 256>>>(Wih1, g_wih1_h, g_wih1_l, n4);
    }
    embed_relu_kernel<<<ROWS, 128>>>(words, embed);

    h0t_kernel<<<64, 256>>>(ehid, 0);
    bfx3_gemm<<<dim3(16, 12), 256, GSMEM>>>(
        g_x_h, g_x_l, g_wih0_h, g_wih0_l, bih0, p_gi,
        ROWS, H3c, EP, EP, H3c);
    gru_layer_kernel<<<128, 256, 90112>>>(Whh0, bhh0, 0);

    h0t_kernel<<<64, 256>>>(ehid, 1);
    bfx3_gemm<<<dim3(16, 12), 256, GSMEM>>>(
        g_hs0_h, g_hs0_l, g_wih1_h, g_wih1_l, bih1, p_gi,
        ROWS, H3c, Hc, Hc, H3c);
    gru_layer_kernel<<<128, 256, 90112>>>(Whh1, bhh1, 1);

    // ---- join: attention ----
    cudaStreamWaitEvent(0, e_proj, 0);
    fph_gemm<2, 0, false, true><<<dim3(1, 2, 32), 256, 3 * 3 * FPL>>>(
        p_catfh, p_catfl, p_projf, nullptr, p_sc, nullptr, nullptr,
        Tc, Sc, Hc, H3c, Sc,
        (long long)Tc * H3c, (long long)Sc * Hc, (long long)Tc * Sc);
    softmax_kernel<<<ROWS, 256>>>();
    fph_gemm<2, 2, false, true><<<dim3(1, 8, 32), 256, 3 * 3 * FPL>>>(
        p_attnfh, p_attnfl, p_encTf, nullptr, nullptr,
        p_catfh + Hc, p_catfl + Hc,
        Tc, 2 * Hc, Sc, Sc, H3c,
        (long long)Tc * Sc, (long long)2 * Hc * Sc, (long long)Tc * H3c);

    // ---- output head ----
    cudaStreamWaitEvent(0, e_aw, 0);
    fph_gemm<2, 1, true, false><<<dim3(16, 12), 256, 3 * 3 * FPL>>>(
        p_catfh, p_catfl, p_awWf, aw_b, nullptr, p_of, nullptr,
        ROWS, H3c, H3c, H3c, H3c, 0, 0, 0);

    cudaStreamWaitEvent(0, e_outw, 0);
    fph_logits<<<304, 256, LSMEM>>>(
        p_of, p_wf, out_b, out, ROWS, Vc, H3c, H3c, Vc);
}

// round 16
// speedup vs baseline: 1.0179x; 1.0179x over previous
#include <cuda_runtime.h>
#include <cuda_bf16.h>
#include <cuda_fp16.h>
#include <cstdint>

#define DI __device__ __forceinline__

// ---------------- problem sizes ----------------
constexpr int Bc = 32, Sc = 256, Tc = 64, T1c = 65;
constexpr int Hc = 512, Ec = 300, Vc = 32000, H3c = 1536;
constexpr int ROWS = Bc * Tc;            // 2048
constexpr int EP = 320;                  // padded embed K

// ---------------- fp32 scratch ----------------
__device__ __align__(16) float g_gi   [ROWS * H3c];
__device__ __align__(16) float g_hta  [Hc * Bc];   // pair-interleaved [(k>>1)][b][k&1]
__device__ __align__(16) float g_htb  [Hc * Bc];
__device__ __align__(16) float g_scores[ROWS * Sc];
__device__ int g_bar_ctr;
__device__ unsigned int g_bar_gen;

// ---------------- bf16 hi/lo planes (gi path only) ----------------
#define PLANES_DECL(name, n) \
    __device__ __align__(16) __nv_bfloat16 name##_hi[n]; \
    __device__ __align__(16) __nv_bfloat16 name##_lo[n];

PLANES_DECL(g_x,     ROWS * EP)
PLANES_DECL(g_wih0,  H3c * EP)
PLANES_DECL(g_wih1,  H3c * Hc)
PLANES_DECL(g_hs0,   ROWS * Hc)

// ---------------- fp16 planes ----------------
__device__ __align__(16) __half g_enc_fh[Bc * Sc * 2 * Hc];
__device__ __align__(16) __half g_enc_fl[Bc * Sc * 2 * Hc];
__device__ __align__(16) __half g_attnW_f[Hc * 2 * Hc];
__device__ __align__(16) __half g_proj_f[Bc * Sc * Hc];
__device__ __align__(16) __half g_encT_f[Bc * 2 * Hc * Sc];
__device__ __align__(16) __half g_attn_fh[ROWS * Sc];
__device__ __align__(16) __half g_attn_fl[ROWS * Sc];
__device__ __align__(16) __half g_cat_fh[ROWS * H3c];
__device__ __align__(16) __half g_cat_fl[ROWS * H3c];
__device__ __align__(16) __half g_awW_f[H3c * H3c];
__device__ __align__(16) __half g_o_f  [ROWS * H3c];
__device__ __align__(16) __half g_outW_f[(long long)Vc * H3c];

// ---------------- helpers ----------------
DI void mma16(float c[4], const uint32_t a[4], const uint32_t b[2]) {
    asm volatile(
        "mma.sync.aligned.m16n8k16.row.col.f32.bf16.bf16.f32 "
        "{%0,%1,%2,%3}, {%4,%5,%6,%7}, {%8,%9}, {%0,%1,%2,%3};"
        : "+f"(c[0]), "+f"(c[1]), "+f"(c[2]), "+f"(c[3])
        : "r"(a[0]), "r"(a[1]), "r"(a[2]), "r"(a[3]), "r"(b[0]), "r"(b[1]));
}
DI void mma16h(float c[4], const uint32_t a[4], const uint32_t b[2]) {
    asm volatile(
        "mma.sync.aligned.m16n8k16.row.col.f32.f16.f16.f32 "
        "{%0,%1,%2,%3}, {%4,%5,%6,%7}, {%8,%9}, {%0,%1,%2,%3};"
        : "+f"(c[0]), "+f"(c[1]), "+f"(c[2]), "+f"(c[3])
        : "r"(a[0]), "r"(a[1]), "r"(a[2]), "r"(a[3]), "r"(b[0]), "r"(b[1]));
}
#define LDSM4(R, addr) \
    asm volatile("ldmatrix.sync.aligned.m8n8.x4.shared.b16 {%0,%1,%2,%3}, [%4];" \
                 : "=r"((R)[0]), "=r"((R)[1]), "=r"((R)[2]), "=r"((R)[3]) : "r"(addr))

DI void cpa16(uint32_t dst, const void* src, bool ok) {
    int sz = ok ? 16 : 0;
    asm volatile("cp.async.cg.shared.global [%0], [%1], 16, %2;\n"
                 :: "r"(dst), "l"(src), "r"(sz));
}
DI void cpa16u(uint32_t dst, const void* src) {
    asm volatile("cp.async.cg.shared.global [%0], [%1], 16;\n"
                 :: "r"(dst), "l"(src));
}
DI void cp_commit() { asm volatile("cp.async.commit_group;\n"); }
DI void cp_wait2()  { asm volatile("cp.async.wait_group 2;\n"); }
DI void cp_wait1()  { asm volatile("cp.async.wait_group 1;\n"); }
DI void cp_wait0()  { asm volatile("cp.async.wait_group 0;\n"); }

DI void splits(float v, __nv_bfloat16& h, __nv_bfloat16& l) {
    h = __float2bfloat16(v);
    l = __float2bfloat16(v - __bfloat162float(h));
}
DI void splith(float v, __half& h, __half& l) {
    h = __float2half_rn(v);
    l = __float2half_rn(v - __half2float(h));
}
// packed f32x2 fma: d = a*b + d  (B300 FFMA2, PTX-only path)
DI void ffma2(unsigned long long& d, unsigned long long a, unsigned long long b) {
    asm("fma.rn.f32x2 %0, %1, %2, %0;" : "+l"(d) : "l"(a), "l"(b));
}
DI float f2sum(unsigned long long v) {
    uint32_t lo = (uint32_t)v, hi = (uint32_t)(v >> 32);
    return __uint_as_float(lo) + __uint_as_float(hi);
}
// pair-interleaved h index: element (k, b) lives at [(k>>1)*64 + 2b + (k&1)]
DI int hidx(int k, int b) { return ((k >> 1) << 6) + (b << 1) + (k & 1); }

// ---------------- split kernels ----------------
__global__ void split_kernel(const float* __restrict__ s,
                             __nv_bfloat16* __restrict__ hi,
                             __nv_bfloat16* __restrict__ lo, int n4) {
    int i = blockIdx.x * blockDim.x + threadIdx.x;
    if (i >= n4) return;
    float4 v = ((const float4*)s)[i];
    __nv_bfloat162 h0 = __floats2bfloat162_rn(v.x, v.y);
    __nv_bfloat162 h1 = __floats2bfloat162_rn(v.z, v.w);
    __nv_bfloat162 l0 = __floats2bfloat162_rn(v.x - __bfloat162float(__low2bfloat16(h0)),
                                              v.y - __bfloat162float(__high2bfloat16(h0)));
    __nv_bfloat162 l1 = __floats2bfloat162_rn(v.z - __bfloat162float(__low2bfloat16(h1)),
                                              v.w - __bfloat162float(__high2bfloat16(h1)));
    ((__nv_bfloat162*)hi)[2 * i] = h0;
    ((__nv_bfloat162*)hi)[2 * i + 1] = h1;
    ((__nv_bfloat162*)lo)[2 * i] = l0;
    ((__nv_bfloat162*)lo)[2 * i + 1] = l1;
}

__global__ void split_pad_kernel(const float* __restrict__ s,
                                 __nv_bfloat16* __restrict__ hi,
                                 __nv_bfloat16* __restrict__ lo,
                                 int N, int K, int Kp) {
    int i = blockIdx.x * blockDim.x + threadIdx.x;
    int total = N * Kp;
    if (i >= total) return;
    int row = i / Kp, col = i % Kp;
    float v = (col < K) ? s[(long long)row * K + col] : 0.f;
    __nv_bfloat16 h, l; splits(v, h, l);
    hi[i] = h; lo[i] = l;
}

__global__ void split_half_kernel(const float* __restrict__ s,
                                  __half* __restrict__ h, int n4) {
    int i = blockIdx.x * blockDim.x + threadIdx.x;
    if (i >= n4) return;
    float4 v = ((const float4*)s)[i];
    ((__half2*)h)[2 * i]     = __floats2half2_rn(v.x, v.y);
    ((__half2*)h)[2 * i + 1] = __floats2half2_rn(v.z, v.w);
}

__global__ void split_half2_kernel(const float* __restrict__ s,
                                   __half* __restrict__ hi,
                                   __half* __restrict__ lo, int n4) {
    int i = blockIdx.x * blockDim.x + threadIdx.x;
    if (i >= n4) return;
    float4 v = ((const float4*)s)[i];
    __half2 h0 = __floats2half2_rn(v.x, v.y);
    __half2 h1 = __floats2half2_rn(v.z, v.w);
    __half2 l0 = __floats2half2_rn(v.x - __half2float(__low2half(h0)),
                                   v.y - __half2float(__high2half(h0)));
    __half2 l1 = __floats2half2_rn(v.z - __half2float(__low2half(h1)),
                                   v.w - __half2float(__high2half(h1)));
    ((__half2*)hi)[2 * i] = h0; ((__half2*)hi)[2 * i + 1] = h1;
    ((__half2*)lo)[2 * i] = l0; ((__half2*)lo)[2 * i + 1] = l1;
}

// ---------------- embed gather + relu -> padded bf16 planes ----------------
__global__ void embed_relu_kernel(const int* __restrict__ words,
                                  const float* __restrict__ embed) {
    int row = blockIdx.x;
    int b = row >> 6, t = row & 63;
    int w = words[b * T1c + t];
    const float* e = embed + (long long)w * Ec;
    for (int i = threadIdx.x; i < EP; i += blockDim.x) {
        float v = (i < Ec) ? fmaxf(e[i], 0.f) : 0.f;
        __nv_bfloat16 h, l; splits(v, h, l);
        g_x_hi[(long long)row * EP + i] = h;
        g_x_lo[(long long)row * EP + i] = l;
    }
}

// ---------------- h0 (pair-interleaved transposed) ----------------
__global__ void h0t_kernel(const float* __restrict__ ehid, int layer) {
    int i = blockIdx.x * blockDim.x + threadIdx.x;
    if (i < Bc * Hc) {
        int b = i >> 9, j = i & 511;
        g_hta[hidx(j, b)] = ehid[layer * Bc * Hc + i] + ehid[(layer + 2) * Bc * Hc + i];
    }
}

// ------------- encoder transpose [b][s][d] -> [b][d][s] fp16 -------------
__global__ void transpose_enc(const float* __restrict__ enc) {
    __shared__ float t[32][33];
    int b = blockIdx.z;
    int d0 = blockIdx.x * 32, s0 = blockIdx.y * 32;
    int tx = threadIdx.x, ty = threadIdx.y;
#pragma unroll
    for (int i = 0; i < 4; i++)
        t[ty + 8 * i][tx] =
            enc[((long long)b * Sc + s0 + ty + 8 * i) * (2 * Hc) + d0 + tx];
    __syncthreads();
#pragma unroll
    for (int i = 0; i < 4; i++) {
        float v = t[tx][ty + 8 * i];
        long long idx = ((long long)b * (2 * Hc) + d0 + ty + 8 * i) * Sc + s0 + tx;
        g_encT_f[idx] = __float2half_rn(v);
    }
}

// ---------------- persistent GRU layer (f32x2 packed FMA) ----------------
// dyn smem: ws[6144] + hs[16384] floats = 90112 B
// h layout (global + smem): pair-interleaved, element (k,b) at [(k>>1)*64+2b+(k&1)]
__global__ void __launch_bounds__(256, 1)
gru_layer_kernel(const float* __restrict__ Whh, const float* __restrict__ bhh,
                 int layer) {
    extern __shared__ float dsm[];
    float* ws = dsm;            // 6144 floats [gate][jl][k]
    float* hs = dsm + 6144;     // 16384 floats, pair-interleaved
    __shared__ float sp[3][4][32];
    int tid = threadIdx.x, bid = blockIdx.x;
    int b = tid & 31, jl = (tid >> 5) & 3, kh = tid >> 7;
    int j = bid * 4 + jl;
    uint32_t hsu = (uint32_t)__cvta_generic_to_shared(hs);

    for (int i = tid; i < 6144; i += 256) {
        int g = i >> 11, r = (i >> 9) & 3, k = i & 511;
        ws[i] = Whh[(long long)(g * Hc + bid * 4 + r) * Hc + k];
    }
    float br = bhh[j], bz = bhh[j + Hc], bn = bhh[j + 2 * Hc];
    __syncthreads();
    const float* wr = &ws[jl * 512];
    const float* wz = &ws[2048 + jl * 512];
    const float* wn = &ws[4096 + jl * 512];

    for (int t = 0; t < Tc; t++) {
        const float* hin = (t & 1) ? g_htb : g_hta;
        float* hout      = (t & 1) ? g_hta : g_htb;
        // stage h (linear copy; layout-agnostic), 4 cp.async groups
#pragma unroll
        for (int g = 0; g < 4; g++) {
            for (int i = tid; i < 1024; i += 256) {
                int idx = g * 1024 + i;
                cpa16u(hsu + idx * 16, hin + idx * 4);
            }
            cp_commit();
        }

        unsigned long long ar2 = 0ull, az2 = 0ull, an2 = 0ull;
        // phase A: k in [kh*128, kh*128+128)  (chunks 0,1 cover k<256)
        cp_wait2();
        __syncthreads();
        int kA = kh * 128;
#pragma unroll 4
        for (int k = kA; k < kA + 128; k += 4) {
            ulonglong2 r2 = *(const ulonglong2*)(wr + k);
            ulonglong2 z2 = *(const ulonglong2*)(wz + k);
            ulonglong2 n2 = *(const ulonglong2*)(wn + k);
            unsigned long long h01 = *(const unsigned long long*)(hs + ((k >> 1) << 6) + (b << 1));
            unsigned long long h23 = *(const unsigned long long*)(hs + (((k >> 1) + 1) << 6) + (b << 1));
            ffma2(ar2, r2.x, h01); ffma2(az2, z2.x, h01); ffma2(an2, n2.x, h01);
            ffma2(ar2, r2.y, h23); ffma2(az2, z2.y, h23); ffma2(an2, n2.y, h23);
        }
        // phase B: k in [256+kh*128, 256+kh*128+128)
        cp_wait0();
        __syncthreads();
        int kB = 256 + kh * 128;
#pragma unroll 4
        for (int k = kB; k < kB + 128; k += 4) {
            ulonglong2 r2 = *(const ulonglong2*)(wr + k);
            ulonglong2 z2 = *(const ulonglong2*)(wz + k);
            ulonglong2 n2 = *(const ulonglong2*)(wn + k);
            unsigned long long h01 = *(const unsigned long long*)(hs + ((k >> 1) << 6) + (b << 1));
            unsigned long long h23 = *(const unsigned long long*)(hs + (((k >> 1) + 1) << 6) + (b << 1));
            ffma2(ar2, r2.x, h01); ffma2(az2, z2.x, h01); ffma2(an2, n2.x, h01);
            ffma2(ar2, r2.y, h23); ffma2(az2, z2.y, h23); ffma2(an2, n2.y, h23);
        }
        float ar = f2sum(ar2), az = f2sum(az2), an = f2sum(an2);
        if (kh) { sp[0][jl][b] = ar; sp[1][jl][b] = az; sp[2][jl][b] = an; }
        __syncthreads();
        if (!kh) {
            ar += sp[0][jl][b]; az += sp[1][jl][b]; an += sp[2][jl][b];
            int row = b * Tc + t;
            const float* g = g_gi + (long long)row * H3c;
            float r = 1.f / (1.f + expf(-(g[j] + ar + br)));
            float z = 1.f / (1.f + expf(-(g[j + Hc] + az + bz)));
            float n = tanhf(g[j + 2 * Hc] + r * (an + bn));
            float hold = hs[hidx(j, b)];
            float hnew = (1.f - z) * n + z * hold;
            __stcg(hout + hidx(j, b), hnew);
            if (layer == 0) {
                __nv_bfloat16 h, l; splits(hnew, h, l);
                g_hs0_hi[(long long)row * Hc + j] = h;
                g_hs0_lo[(long long)row * Hc + j] = l;
            } else {
                __half h, l; splith(hnew, h, l);
                g_cat_fh[(long long)row * H3c + j] = h;
                g_cat_fl[(long long)row * H3c + j] = l;
            }
        }
        __syncthreads();
        __threadfence();
        if (tid == 0) {
            unsigned int gen = atomicAdd(&g_bar_gen, 0u);
            int old = atomicAdd(&g_bar_ctr, 1);
            if (old == (int)gridDim.x - 1) {
                atomicExch(&g_bar_ctr, 0);
                __threadfence();
                atomicAdd(&g_bar_gen, 1u);
            } else {
                while (atomicAdd(&g_bar_gen, 0u) == gen) {}
            }
        }
        __syncthreads();
    }
}

// ---------------- softmax (256 wide) -> attn fp16 planes ----------------
__global__ void softmax_kernel() {
    int row = blockIdx.x, tid = threadIdx.x;
    __shared__ float sm_[8], ss_[8];
    float v = g_scores[(long long)row * Sc + tid];
    float m = v;
#pragma unroll
    for (int o = 16; o; o >>= 1) m = fmaxf(m, __shfl_xor_sync(~0u, m, o));
    if ((tid & 31) == 0) sm_[tid >> 5] = m;
    __syncthreads();
    float mm = sm_[0];
#pragma unroll
    for (int i = 1; i < 8; i++) mm = fmaxf(mm, sm_[i]);
    float e = expf(v - mm);
    float s = e;
#pragma unroll
    for (int o = 16; o; o >>= 1) s += __shfl_xor_sync(~0u, s, o);
    if ((tid & 31) == 0) ss_[tid >> 5] = s;
    __syncthreads();
    float tot = 0.f;
#pragma unroll
    for (int i = 0; i < 8; i++) tot += ss_[i];
    float p = e / tot;
    __half h, l; splith(p, h, l);
    g_attn_fh[(long long)row * Sc + tid] = h;
    g_attn_fl[(long long)row * Sc + tid] = l;
}

// ======================= bf16x3 pipelined tensor GEMM (gi only) ==============
constexpr int GSTAGE = 32768;
constexpr int GSMEM  = 3 * GSTAGE;

__global__ void __launch_bounds__(256, 1)
bfx3_gemm(const __nv_bfloat16* __restrict__ Ahi, const __nv_bfloat16* __restrict__ Alo,
          const __nv_bfloat16* __restrict__ Bhi, const __nv_bfloat16* __restrict__ Blo,
          const float* __restrict__ bias, float* __restrict__ C,
          int M, int N, int K, int lda, int ldc) {
    extern __shared__ char smem[];
    uint32_t su = (uint32_t)__cvta_generic_to_shared(smem);

    const int m0 = blockIdx.x * 128, n0 = blockIdx.y * 128;
    const int tid = threadIdx.x;
    const int lane = tid & 31, wid = tid >> 5;
    const int wm = wid & 1, wn = wid >> 1;
    const int lr = lane >> 2, lc = lane & 3;

    float c[4][4][4] = {};

    auto issue_load = [&](int stage, int kt) {
        int kb = kt * 32;
        uint32_t sb = su + stage * GSTAGE;
#pragma unroll
        for (int i = 0; i < 8; i++) {
            int chunkid = tid + 256 * i;
            int plane = chunkid >> 9;
            int w = chunkid & 511;
            int r = w >> 2, cck = w & 3;
            uint32_t dst = sb + plane * 8192 + r * 64 + ((cck ^ ((r >> 1) & 3)) << 4);
            const __nv_bfloat16* src;
            if (plane < 2)
                src = (plane == 0 ? Ahi : Alo) + (long long)(m0 + r) * lda + kb + cck * 8;
            else
                src = (plane == 2 ? Bhi : Blo) + (long long)(n0 + r) * K + kb + cck * 8;
            cpa16u(dst, src);
        }
    };

    const int kt_count = K >> 5;
    issue_load(0, 0); cp_commit();
    issue_load(1, 1); cp_commit();

    for (int kt = 0; kt < kt_count; kt++) {
        if (kt + 2 < kt_count) cp_wait1(); else cp_wait0();
        __syncthreads();
        if (kt + 2 < kt_count) { issue_load((kt + 2) % 3, kt + 2); cp_commit(); }

        uint32_t sb = su + (kt % 3) * GSTAGE;
#pragma unroll
        for (int ks = 0; ks < 2; ks++) {
            uint32_t ah[4][4], al[4][4], bh[2][4], bl[2][4];
#pragma unroll
            for (int mi = 0; mi < 4; mi++) {
                int row = wm * 64 + mi * 16 + (lane & 15);
                int ch = 2 * ks + (lane >> 4);
                uint32_t a = sb + row * 64 + ((ch ^ ((row >> 1) & 3)) << 4);
                LDSM4(ah[mi], a);
                LDSM4(al[mi], a + 8192);
            }
#pragma unroll
            for (int np = 0; np < 2; np++) {
                int row = wn * 32 + np * 16 + ((lane >> 4) << 3) + (lane & 7);
                int ch = 2 * ks + ((lane >> 3) & 1);
                uint32_t a = sb + 16384 + row * 64 + ((ch ^ ((row >> 1) & 3)) << 4);
                LDSM4(bh[np], a);
                LDSM4(bl[np], a + 8192);
            }
#pragma unroll
            for (int mi = 0; mi < 4; mi++)
#pragma unroll
                for (int ni = 0; ni < 4; ni++)
                    mma16(c[mi][ni], ah[mi], &bh[ni >> 1][(ni & 1) * 2]);
#pragma unroll
            for (int mi = 0; mi < 4; mi++)
#pragma unroll
                for (int ni = 0; ni < 4; ni++)
                    mma16(c[mi][ni], ah[mi], &bl[ni >> 1][(ni & 1) * 2]);
#pragma unroll
            for (int mi = 0; mi < 4; mi++)
#pragma unroll
                for (int ni = 0; ni < 4; ni++)
                    mma16(c[mi][ni], al[mi], &bh[ni >> 1][(ni & 1) * 2]);
        }
        __syncthreads();
    }

#pragma unroll
    for (int mi = 0; mi < 4; mi++) {
#pragma unroll
        for (int ni = 0; ni < 4; ni++) {
            int row = m0 + wm * 64 + mi * 16 + lr;
            int col = n0 + wn * 32 + ni * 8 + lc * 2;
            float b0 = bias[col], b1 = bias[col + 1];
            *(float2*)(C + (long long)row * ldc + col) =
                make_float2(c[mi][ni][0] + b0, c[mi][ni][1] + b1);
            *(float2*)(C + (long long)(row + 8) * ldc + col) =
                make_float2(c[mi][ni][2] + b0, c[mi][ni][3] + b1);
        }
    }
}

// ============ fp16 pipelined GEMM: C = (sum A-terms) @ Bf^T (+bias) ============
constexpr int FPL = 8192;

template <int AT, int OUT, bool RELU, bool GUARD>
__global__ void __launch_bounds__(256, 2)
fph_gemm(const __half* __restrict__ Ahi, const __half* __restrict__ Alo,
         const __half* __restrict__ Bf, const float* __restrict__ bias,
         float* __restrict__ C, __half* __restrict__ Ch, __half* __restrict__ Cl,
         int M, int N, int K, int lda, int ldc,
         long long sA, long long sB, long long sC) {
    extern __shared__ char smem[];
    uint32_t su = (uint32_t)__cvta_generic_to_shared(smem);
    constexpr int NPL = AT + 1;
    constexpr int STG = NPL * FPL;

    Ahi += (long long)blockIdx.z * sA;
    if (AT == 2) Alo += (long long)blockIdx.z * sA;
    Bf += (long long)blockIdx.z * sB;

    const int m0 = blockIdx.x * 128, n0 = blockIdx.y * 128;
    const int tid = threadIdx.x;
    const int lane = tid & 31, wid = tid >> 5;
    const int wm = wid & 1, wn = wid >> 1;
    const int lr = lane >> 2, lc = lane & 3;

    float c[4][4][4] = {};

    auto issue_load = [&](int stage, int kt) {
        int kb = kt * 32;
        uint32_t sb = su + stage * STG;
#pragma unroll
        for (int i = 0; i < NPL * 2; i++) {
            int chunkid = tid + 256 * i;
            int plane = chunkid >> 9;
            int w = chunkid & 511;
            int r = w >> 2, cck = w & 3;
            uint32_t dst = sb + plane * FPL + r * 64 + ((cck ^ ((r >> 1) & 3)) << 4);
            const __half* src;
            bool ok = true;
            if (plane < AT) {
                src = (plane == 0 ? Ahi : Alo) + (long long)(m0 + r) * lda + kb + cck * 8;
                if (GUARD) ok = (m0 + r) < M;
            } else {
                src = Bf + (long long)(n0 + r) * K + kb + cck * 8;
            }
            if (GUARD) cpa16(dst, src, ok); else cpa16u(dst, src);
        }
    };

    const int kt_count = K >> 5;
    issue_load(0, 0); cp_commit();
    issue_load(1, 1); cp_commit();

    for (int kt = 0; kt < kt_count; kt++) {
        if (kt + 2 < kt_count) cp_wait1(); else cp_wait0();
        __syncthreads();
        if (kt + 2 < kt_count) { issue_load((kt + 2) % 3, kt + 2); cp_commit(); }

        uint32_t sb = su + (kt % 3) * STG;
#pragma unroll
        for (int ks = 0; ks < 2; ks++) {
            uint32_t ah[AT][4][4], bh[2][4];
#pragma unroll
            for (int t = 0; t < AT; t++)
#pragma unroll
                for (int mi = 0; mi < 4; mi++) {
                    int row = wm * 64 + mi * 16 + (lane & 15);
                    int ch = 2 * ks + (lane >> 4);
                    uint32_t a = sb + t * FPL + row * 64 + ((ch ^ ((row >> 1) & 3)) << 4);
                    LDSM4(ah[t][mi], a);
                }
#pragma unroll
            for (int np = 0; np < 2; np++) {
                int row = wn * 32 + np * 16 + ((lane >> 4) << 3) + (lane & 7);
                int ch = 2 * ks + ((lane >> 3) & 1);
                uint32_t a = sb + AT * FPL + row * 64 + ((ch ^ ((row >> 1) & 3)) << 4);
                LDSM4(bh[np], a);
            }
#pragma unroll
            for (int t = 0; t < AT; t++)
#pragma unroll
                for (int mi = 0; mi < 4; mi++)
#pragma unroll
                    for (int ni = 0; ni < 4; ni++)
                        mma16h(c[mi][ni], ah[t][mi], &bh[ni >> 1][(ni & 1) * 2]);
        }
        __syncthreads();
    }

#pragma unroll
    for (int mi = 0; mi < 4; mi++) {
#pragma unroll
        for (int ni = 0; ni < 4; ni++) {
            int row = m0 + wm * 64 + mi * 16 + lr;
            int col = n0 + wn * 32 + ni * 8 + lc * 2;
            float b0 = bias ? bias[col] : 0.f;
            float b1 = bias ? bias[col + 1] : 0.f;
            float v0 = c[mi][ni][0] + b0, v1 = c[mi][ni][1] + b1;
            float v2 = c[mi][ni][2] + b0, v3 = c[mi][ni][3] + b1;
            if (RELU) {
                v0 = fmaxf(v0, 0.f); v1 = fmaxf(v1, 0.f);
                v2 = fmaxf(v2, 0.f); v3 = fmaxf(v3, 0.f);
            }
            bool ok0 = !GUARD || row < M;
            bool ok1 = !GUARD || (row + 8) < M;
            if (OUT == 0) {
                float* Cz = C + (long long)blockIdx.z * sC;
                if (ok0)
                    *(float2*)(Cz + (long long)row * ldc + col) = make_float2(v0, v1);
                if (ok1)
                    *(float2*)(Cz + (long long)(row + 8) * ldc + col) = make_float2(v2, v3);
            } else if (OUT == 1) {
                __half* Co = Ch + (long long)blockIdx.z * sC;
                if (ok0)
                    *(__half2*)(Co + (long long)row * ldc + col) = __floats2half2_rn(v0, v1);
                if (ok1)
                    *(__half2*)(Co + (long long)(row + 8) * ldc + col) = __floats2half2_rn(v2, v3);
            } else {
                __half* Coh = Ch + (long long)blockIdx.z * sC;
                __half* Col = Cl + (long long)blockIdx.z * sC;
                if (ok0) {
                    __half2 h = __floats2half2_rn(v0, v1);
                    __half2 l = __floats2half2_rn(v0 - __half2float(__low2half(h)),
                                                  v1 - __half2float(__high2half(h)));
                    *(__half2*)(Coh + (long long)row * ldc + col) = h;
                    *(__half2*)(Col + (long long)row * ldc + col) = l;
                }
                if (ok1) {
                    __half2 h = __floats2half2_rn(v2, v3);
                    __half2 l = __floats2half2_rn(v2 - __half2float(__low2half(h)),
                                                  v3 - __half2float(__high2half(h)));
                    *(__half2*)(Coh + (long long)(row + 8) * ldc + col) = h;
                    *(__half2*)(Col + (long long)(row + 8) * ldc + col) = l;
                }
            }
        }
    }
}

// ---------------- host launch ----------------
extern "C" void kernel_launch(void* const* d_in, const int* in_sizes, int n_in,
                              void* d_out, int out_size) {
    (void)in_sizes; (void)n_in; (void)out_size;
    const float* enc    = (const float*)d_in[0];
    const float* ehid   = (const float*)d_in[1];
    const int*   words  = (const int*)d_in[2];
    const float* embed  = (const float*)d_in[3];
    const float* Wih0   = (const float*)d_in[4];
    const float* Whh0   = (const float*)d_in[5];
    const float* bih0   = (const float*)d_in[6];
    const float* bhh0   = (const float*)d_in[7];
    const float* Wih1   = (const float*)d_in[8];
    const float* Whh1   = (const float*)d_in[9];
    const float* bih1   = (const float*)d_in[10];
    const float* bhh1   = (const float*)d_in[11];
    const float* attn_W = (const float*)d_in[12];
    const float* attn_b = (const float*)d_in[13];
    const float* aw_W   = (const float*)d_in[14];
    const float* aw_b   = (const float*)d_in[15];
    const float* out_W  = (const float*)d_in[16];
    const float* out_b  = (const float*)d_in[17];
    float* out = (float*)d_out;

    float *p_gi, *p_sc;
    cudaGetSymbolAddress((void**)&p_gi, g_gi);
    cudaGetSymbolAddress((void**)&p_sc, g_scores);

#define GETP(sym) \
    __nv_bfloat16 *sym##_h, *sym##_l; \
    cudaGetSymbolAddress((void**)&sym##_h, sym##_hi); \
    cudaGetSymbolAddress((void**)&sym##_l, sym##_lo);
    GETP(g_x) GETP(g_wih0) GETP(g_wih1) GETP(g_hs0)
#undef GETP
    __half *p_encfh, *p_encfl, *p_awnf, *p_projf, *p_encTf;
    __half *p_attnfh, *p_attnfl, *p_catfh, *p_catfl, *p_awWf, *p_of, *p_wf;
    cudaGetSymbolAddress((void**)&p_encfh,  g_enc_fh);
    cudaGetSymbolAddress((void**)&p_encfl,  g_enc_fl);
    cudaGetSymbolAddress((void**)&p_awnf,   g_attnW_f);
    cudaGetSymbolAddress((void**)&p_projf,  g_proj_f);
    cudaGetSymbolAddress((void**)&p_encTf,  g_encT_f);
    cudaGetSymbolAddress((void**)&p_attnfh, g_attn_fh);
    cudaGetSymbolAddress((void**)&p_attnfl, g_attn_fl);
    cudaGetSymbolAddress((void**)&p_catfh,  g_cat_fh);
    cudaGetSymbolAddress((void**)&p_catfl,  g_cat_fl);
    cudaGetSymbolAddress((void**)&p_awWf,   g_awW_f);
    cudaGetSymbolAddress((void**)&p_of,     g_o_f);
    cudaGetSymbolAddress((void**)&p_wf,     g_outW_f);

    cudaFuncSetAttribute(bfx3_gemm,
                         cudaFuncAttributeMaxDynamicSharedMemorySize, GSMEM);
    cudaFuncSetAttribute((fph_gemm<2, 1, false, false>),
                         cudaFuncAttributeMaxDynamicSharedMemorySize, 3 * 3 * FPL);
    cudaFuncSetAttribute((fph_gemm<2, 0, false, true>),
                         cudaFuncAttributeMaxDynamicSharedMemorySize, 3 * 3 * FPL);
    cudaFuncSetAttribute((fph_gemm<2, 2, false, true>),
                         cudaFuncAttributeMaxDynamicSharedMemorySize, 3 * 3 * FPL);
    cudaFuncSetAttribute((fph_gemm<2, 1, true, false>),
                         cudaFuncAttributeMaxDynamicSharedMemorySize, 3 * 3 * FPL);
    cudaFuncSetAttribute((fph_gemm<1, 0, false, false>),
                         cudaFuncAttributeMaxDynamicSharedMemorySize, 3 * 2 * FPL);
    cudaFuncSetAttribute(gru_layer_kernel,
                         cudaFuncAttributeMaxDynamicSharedMemorySize, 90112);

    // ---- streams/events (frozen round-10 structure) ----
    static cudaStream_t s1 = nullptr, s2 = nullptr;
    static cudaEvent_t e0 = nullptr, e_aw = nullptr, e_outw = nullptr, e_proj = nullptr;
    if (!s1) {
        cudaStreamCreateWithFlags(&s1, cudaStreamNonBlocking);
        cudaStreamCreateWithFlags(&s2, cudaStreamNonBlocking);
        cudaEventCreateWithFlags(&e0,     cudaEventDisableTiming);
        cudaEventCreateWithFlags(&e_aw,   cudaEventDisableTiming);
        cudaEventCreateWithFlags(&e_outw, cudaEventDisableTiming);
        cudaEventCreateWithFlags(&e_proj, cudaEventDisableTiming);
    }

    // fork
    cudaEventRecord(e0, 0);
    cudaStreamWaitEvent(s1, e0, 0);
    cudaStreamWaitEvent(s2, e0, 0);

    // ---- s1: weight conversions for the output head ----
    {
        int n4 = H3c * H3c / 4;
        split_half_kernel<<<(n4 + 255) / 256, 256, 0, s1>>>(aw_W, p_awWf, n4);
        cudaEventRecord(e_aw, s1);
        n4 = Vc * H3c / 4;
        split_half_kernel<<<(n4 + 255) / 256, 256, 0, s1>>>(out_W, p_wf, n4);
        cudaEventRecord(e_outw, s1);
    }

    // ---- s2: attention prep + proj GEMM ----
    {
        int n4 = Bc * Sc * 2 * Hc / 4;
        split_half2_kernel<<<(n4 + 255) / 256, 256, 0, s2>>>(enc, p_encfh, p_encfl, n4);
        n4 = Hc * 2 * Hc / 4;
        split_half_kernel<<<(n4 + 255) / 256, 256, 0, s2>>>(attn_W, p_awnf, n4);
        transpose_enc<<<dim3(32, 8, 32), dim3(32, 8), 0, s2>>>(enc);
        fph_gemm<2, 1, false, false><<<dim3(64, 4), 256, 3 * 3 * FPL, s2>>>(
            p_encfh, p_encfl, p_awnf, attn_b, nullptr, p_projf, nullptr,
            Bc * Sc, Hc, 2 * Hc, 2 * Hc, Hc, 0, 0, 0);
        cudaEventRecord(e_proj, s2);
    }

    // ---- main stream: GRU critical path ----
    {
        int tot = H3c * EP;
        split_pad_kernel<<<(tot + 255) / 256, 256>>>(Wih0, g_wih0_h, g_wih0_l,
                                                     H3c, Ec, EP);
        int n4 = H3c * Hc / 4;
        split_kernel<<<(n4 + 255) / 256, 256>>>(Wih1, g_wih1_h, g_wih1_l, n4);
    }
    embed_relu_kernel<<<ROWS, 128>>>(words, embed);

    h0t_kernel<<<64, 256>>>(ehid, 0);
    bfx3_gemm<<<dim3(16, 12), 256, GSMEM>>>(
        g_x_h, g_x_l, g_wih0_h, g_wih0_l, bih0, p_gi,
        ROWS, H3c, EP, EP, H3c);
    gru_layer_kernel<<<128, 256, 90112>>>(Whh0, bhh0, 0);

    h0t_kernel<<<64, 256>>>(ehid, 1);
    bfx3_gemm<<<dim3(16, 12), 256, GSMEM>>>(
        g_hs0_h, g_hs0_l, g_wih1_h, g_wih1_l, bih1, p_gi,
        ROWS, H3c, Hc, Hc, H3c);
    gru_layer_kernel<<<128, 256, 90112>>>(Whh1, bhh1, 1);

    // ---- join: attention ----
    cudaStreamWaitEvent(0, e_proj, 0);
    fph_gemm<2, 0, false, true><<<dim3(1, 2, 32), 256, 3 * 3 * FPL>>>(
        p_catfh, p_catfl, p_projf, nullptr, p_sc, nullptr, nullptr,
        Tc, Sc, Hc, H3c, Sc,
        (long long)Tc * H3c, (long long)Sc * Hc, (long long)Tc * Sc);
    softmax_kernel<<<ROWS, 256>>>();
    fph_gemm<2, 2, false, true><<<dim3(1, 8, 32), 256, 3 * 3 * FPL>>>(
        p_attnfh, p_attnfl, p_encTf, nullptr, nullptr,
        p_catfh + Hc, p_catfl + Hc,
        Tc, 2 * Hc, Sc, Sc, H3c,
        (long long)Tc * Sc, (long long)2 * Hc * Sc, (long long)Tc * H3c);

    // ---- output head ----
    cudaStreamWaitEvent(0, e_aw, 0);
    fph_gemm<2, 1, true, false><<<dim3(16, 12), 256, 3 * 3 * FPL>>>(
        p_catfh, p_catfl, p_awWf, aw_b, nullptr, p_of, nullptr,
        ROWS, H3c, H3c, H3c, H3c, 0, 0, 0);

    cudaStreamWaitEvent(0, e_outw, 0);
    fph_gemm<1, 0, false, false><<<dim3(16, 250), 256, 3 * 2 * FPL>>>(
        p_of, nullptr, p_wf, out_b, out, nullptr, nullptr,
        ROWS, Vc, H3c, H3c, Vc, 0, 0, 0);
}

// round 17
// speedup vs baseline: 1.0850x; 1.0659x over previous
#include <cuda_runtime.h>
#include <cuda_bf16.h>
#include <cuda_fp16.h>
#include <cstdint>

#define DI __device__ __forceinline__

// ---------------- problem sizes ----------------
constexpr int Bc = 32, Sc = 256, Tc = 64, T1c = 65;
constexpr int Hc = 512, Ec = 300, Vc = 32000, H3c = 1536;
constexpr int ROWS = Bc * Tc;            // 2048
constexpr int EP = 320;                  // padded embed K

// ---------------- fp32 scratch ----------------
__device__ __align__(16) float g_gi   [ROWS * H3c];
__device__ __align__(16) float g_hta  [Hc * Bc];   // pair-interleaved [(k>>1)][b][k&1]
__device__ __align__(16) float g_htb  [Hc * Bc];
__device__ __align__(16) float g_scores[ROWS * Sc];
__device__ int g_bar_ctr;
__device__ unsigned int g_bar_gen;

// ---------------- bf16 hi/lo planes (gi path only) ----------------
#define PLANES_DECL(name, n) \
    __device__ __align__(16) __nv_bfloat16 name##_hi[n]; \
    __device__ __align__(16) __nv_bfloat16 name##_lo[n];

PLANES_DECL(g_x,     ROWS * EP)
PLANES_DECL(g_wih0,  H3c * EP)
PLANES_DECL(g_wih1,  H3c * Hc)
PLANES_DECL(g_hs0,   ROWS * Hc)

// ---------------- fp16 planes ----------------
__device__ __align__(16) __half g_enc_fh[Bc * Sc * 2 * Hc];
__device__ __align__(16) __half g_enc_fl[Bc * Sc * 2 * Hc];
__device__ __align__(16) __half g_attnW_f[Hc * 2 * Hc];
__device__ __align__(16) __half g_proj_f[Bc * Sc * Hc];
__device__ __align__(16) __half g_encT_f[Bc * 2 * Hc * Sc];
__device__ __align__(16) __half g_attn_fh[ROWS * Sc];
__device__ __align__(16) __half g_attn_fl[ROWS * Sc];
__device__ __align__(16) __half g_cat_fh[ROWS * H3c];
__device__ __align__(16) __half g_cat_fl[ROWS * H3c];
__device__ __align__(16) __half g_awW_f[H3c * H3c];
__device__ __align__(16) __half g_o_f  [ROWS * H3c];
__device__ __align__(16) __half g_outW_f[(long long)Vc * H3c];

// ---------------- helpers ----------------
DI void mma16(float c[4], const uint32_t a[4], const uint32_t b[2]) {
    asm volatile(
        "mma.sync.aligned.m16n8k16.row.col.f32.bf16.bf16.f32 "
        "{%0,%1,%2,%3}, {%4,%5,%6,%7}, {%8,%9}, {%0,%1,%2,%3};"
        : "+f"(c[0]), "+f"(c[1]), "+f"(c[2]), "+f"(c[3])
        : "r"(a[0]), "r"(a[1]), "r"(a[2]), "r"(a[3]), "r"(b[0]), "r"(b[1]));
}
DI void mma16h(float c[4], const uint32_t a[4], const uint32_t b[2]) {
    asm volatile(
        "mma.sync.aligned.m16n8k16.row.col.f32.f16.f16.f32 "
        "{%0,%1,%2,%3}, {%4,%5,%6,%7}, {%8,%9}, {%0,%1,%2,%3};"
        : "+f"(c[0]), "+f"(c[1]), "+f"(c[2]), "+f"(c[3])
        : "r"(a[0]), "r"(a[1]), "r"(a[2]), "r"(a[3]), "r"(b[0]), "r"(b[1]));
}
#define LDSM4(R, addr) \
    asm volatile("ldmatrix.sync.aligned.m8n8.x4.shared.b16 {%0,%1,%2,%3}, [%4];" \
                 : "=r"((R)[0]), "=r"((R)[1]), "=r"((R)[2]), "=r"((R)[3]) : "r"(addr))

DI void cpa16(uint32_t dst, const void* src, bool ok) {
    int sz = ok ? 16 : 0;
    asm volatile("cp.async.cg.shared.global [%0], [%1], 16, %2;\n"
                 :: "r"(dst), "l"(src), "r"(sz));
}
DI void cpa16u(uint32_t dst, const void* src) {
    asm volatile("cp.async.cg.shared.global [%0], [%1], 16;\n"
                 :: "r"(dst), "l"(src));
}
DI void cp_commit() { asm volatile("cp.async.commit_group;\n"); }
DI void cp_wait2()  { asm volatile("cp.async.wait_group 2;\n"); }
DI void cp_wait1()  { asm volatile("cp.async.wait_group 1;\n"); }
DI void cp_wait0()  { asm volatile("cp.async.wait_group 0;\n"); }

DI void splits(float v, __nv_bfloat16& h, __nv_bfloat16& l) {
    h = __float2bfloat16(v);
    l = __float2bfloat16(v - __bfloat162float(h));
}
DI void splith(float v, __half& h, __half& l) {
    h = __float2half_rn(v);
    l = __float2half_rn(v - __half2float(h));
}
// packed f32x2 fma: d = a*b + d  (B300 FFMA2, PTX-only path)
DI void ffma2(unsigned long long& d, unsigned long long a, unsigned long long b) {
    asm("fma.rn.f32x2 %0, %1, %2, %0;" : "+l"(d) : "l"(a), "l"(b));
}
DI float f2sum(unsigned long long v) {
    uint32_t lo = (uint32_t)v, hi = (uint32_t)(v >> 32);
    return __uint_as_float(lo) + __uint_as_float(hi);
}
// pair-interleaved h index: element (k, b) lives at [(k>>1)*64 + 2b + (k&1)]
DI int hidx(int k, int b) { return ((k >> 1) << 6) + (b << 1) + (k & 1); }

// ---------------- split kernels ----------------
__global__ void split_kernel(const float* __restrict__ s,
                             __nv_bfloat16* __restrict__ hi,
                             __nv_bfloat16* __restrict__ lo, int n4) {
    int i = blockIdx.x * blockDim.x + threadIdx.x;
    if (i >= n4) return;
    float4 v = ((const float4*)s)[i];
    __nv_bfloat162 h0 = __floats2bfloat162_rn(v.x, v.y);
    __nv_bfloat162 h1 = __floats2bfloat162_rn(v.z, v.w);
    __nv_bfloat162 l0 = __floats2bfloat162_rn(v.x - __bfloat162float(__low2bfloat16(h0)),
                                              v.y - __bfloat162float(__high2bfloat16(h0)));
    __nv_bfloat162 l1 = __floats2bfloat162_rn(v.z - __bfloat162float(__low2bfloat16(h1)),
                                              v.w - __bfloat162float(__high2bfloat16(h1)));
    ((__nv_bfloat162*)hi)[2 * i] = h0;
    ((__nv_bfloat162*)hi)[2 * i + 1] = h1;
    ((__nv_bfloat162*)lo)[2 * i] = l0;
    ((__nv_bfloat162*)lo)[2 * i + 1] = l1;
}

__global__ void split_pad_kernel(const float* __restrict__ s,
                                 __nv_bfloat16* __restrict__ hi,
                                 __nv_bfloat16* __restrict__ lo,
                                 int N, int K, int Kp) {
    int i = blockIdx.x * blockDim.x + threadIdx.x;
    int total = N * Kp;
    if (i >= total) return;
    int row = i / Kp, col = i % Kp;
    float v = (col < K) ? s[(long long)row * K + col] : 0.f;
    __nv_bfloat16 h, l; splits(v, h, l);
    hi[i] = h; lo[i] = l;
}

__global__ void split_half_kernel(const float* __restrict__ s,
                                  __half* __restrict__ h, int n4) {
    int i = blockIdx.x * blockDim.x + threadIdx.x;
    if (i >= n4) return;
    float4 v = ((const float4*)s)[i];
    ((__half2*)h)[2 * i]     = __floats2half2_rn(v.x, v.y);
    ((__half2*)h)[2 * i + 1] = __floats2half2_rn(v.z, v.w);
}

__global__ void split_half2_kernel(const float* __restrict__ s,
                                   __half* __restrict__ hi,
                                   __half* __restrict__ lo, int n4) {
    int i = blockIdx.x * blockDim.x + threadIdx.x;
    if (i >= n4) return;
    float4 v = ((const float4*)s)[i];
    __half2 h0 = __floats2half2_rn(v.x, v.y);
    __half2 h1 = __floats2half2_rn(v.z, v.w);
    __half2 l0 = __floats2half2_rn(v.x - __half2float(__low2half(h0)),
                                   v.y - __half2float(__high2half(h0)));
    __half2 l1 = __floats2half2_rn(v.z - __half2float(__low2half(h1)),
                                   v.w - __half2float(__high2half(h1)));
    ((__half2*)hi)[2 * i] = h0; ((__half2*)hi)[2 * i + 1] = h1;
    ((__half2*)lo)[2 * i] = l0; ((__half2*)lo)[2 * i + 1] = l1;
}

// ---------------- embed gather + relu -> padded bf16 planes ----------------
__global__ void embed_relu_kernel(const int* __restrict__ words,
                                  const float* __restrict__ embed) {
    int row = blockIdx.x;
    int b = row >> 6, t = row & 63;
    int w = words[b * T1c + t];
    const float* e = embed + (long long)w * Ec;
    for (int i = threadIdx.x; i < EP; i += blockDim.x) {
        float v = (i < Ec) ? fmaxf(e[i], 0.f) : 0.f;
        __nv_bfloat16 h, l; splits(v, h, l);
        g_x_hi[(long long)row * EP + i] = h;
        g_x_lo[(long long)row * EP + i] = l;
    }
}

// ---------------- h0 (pair-interleaved transposed) ----------------
__global__ void h0t_kernel(const float* __restrict__ ehid, int layer) {
    int i = blockIdx.x * blockDim.x + threadIdx.x;
    if (i < Bc * Hc) {
        int b = i >> 9, j = i & 511;
        g_hta[hidx(j, b)] = ehid[layer * Bc * Hc + i] + ehid[(layer + 2) * Bc * Hc + i];
    }
}

// ------------- encoder transpose [b][s][d] -> [b][d][s] fp16 -------------
__global__ void transpose_enc(const float* __restrict__ enc) {
    __shared__ float t[32][33];
    int b = blockIdx.z;
    int d0 = blockIdx.x * 32, s0 = blockIdx.y * 32;
    int tx = threadIdx.x, ty = threadIdx.y;
#pragma unroll
    for (int i = 0; i < 4; i++)
        t[ty + 8 * i][tx] =
            enc[((long long)b * Sc + s0 + ty + 8 * i) * (2 * Hc) + d0 + tx];
    __syncthreads();
#pragma unroll
    for (int i = 0; i < 4; i++) {
        float v = t[tx][ty + 8 * i];
        long long idx = ((long long)b * (2 * Hc) + d0 + ty + 8 * i) * Sc + s0 + tx;
        g_encT_f[idx] = __float2half_rn(v);
    }
}

// ---------------- persistent GRU layer (f32x2 FMA, fast barrier) ----------------
// dyn smem: ws[6144] + hs[16384] floats = 90112 B
__global__ void __launch_bounds__(256, 1)
gru_layer_kernel(const float* __restrict__ Whh, const float* __restrict__ bhh,
                 int layer) {
    extern __shared__ float dsm[];
    float* ws = dsm;            // 6144 floats [gate][jl][k]
    float* hs = dsm + 6144;     // 16384 floats, pair-interleaved
    __shared__ float sp[3][4][32];
    int tid = threadIdx.x, bid = blockIdx.x;
    int b = tid & 31, jl = (tid >> 5) & 3, kh = tid >> 7;
    int j = bid * 4 + jl;
    uint32_t hsu = (uint32_t)__cvta_generic_to_shared(hs);
    int* pctr = &g_bar_ctr;
    unsigned int* pgen = &g_bar_gen;

    for (int i = tid; i < 6144; i += 256) {
        int g = i >> 11, r = (i >> 9) & 3, k = i & 511;
        ws[i] = Whh[(long long)(g * Hc + bid * 4 + r) * Hc + k];
    }
    float br = bhh[j], bz = bhh[j + Hc], bn = bhh[j + 2 * Hc];
    __syncthreads();
    const float* wr = &ws[jl * 512];
    const float* wz = &ws[2048 + jl * 512];
    const float* wn = &ws[4096 + jl * 512];

    for (int t = 0; t < Tc; t++) {
        const float* hin = (t & 1) ? g_htb : g_hta;
        float* hout      = (t & 1) ? g_hta : g_htb;
        // prefetch gi for this step (independent of h; hides L2 latency)
        float g0 = 0.f, g1 = 0.f, g2 = 0.f;
        if (!kh) {
            const float* g = g_gi + (long long)(b * Tc + t) * H3c;
            g0 = __ldg(g + j); g1 = __ldg(g + j + Hc); g2 = __ldg(g + j + 2 * Hc);
        }
        // stage h (4 cp.async groups)
#pragma unroll
        for (int g = 0; g < 4; g++) {
            for (int i = tid; i < 1024; i += 256) {
                int idx = g * 1024 + i;
                cpa16u(hsu + idx * 16, hin + idx * 4);
            }
            cp_commit();
        }

        unsigned long long ar2 = 0ull, az2 = 0ull, an2 = 0ull;
        cp_wait2();
        __syncthreads();
        int kA = kh * 128;
#pragma unroll 4
        for (int k = kA; k < kA + 128; k += 4) {
            ulonglong2 r2 = *(const ulonglong2*)(wr + k);
            ulonglong2 z2 = *(const ulonglong2*)(wz + k);
            ulonglong2 n2 = *(const ulonglong2*)(wn + k);
            unsigned long long h01 = *(const unsigned long long*)(hs + ((k >> 1) << 6) + (b << 1));
            unsigned long long h23 = *(const unsigned long long*)(hs + (((k >> 1) + 1) << 6) + (b << 1));
            ffma2(ar2, r2.x, h01); ffma2(az2, z2.x, h01); ffma2(an2, n2.x, h01);
            ffma2(ar2, r2.y, h23); ffma2(az2, z2.y, h23); ffma2(an2, n2.y, h23);
        }
        cp_wait0();
        __syncthreads();
        int kB = 256 + kh * 128;
#pragma unroll 4
        for (int k = kB; k < kB + 128; k += 4) {
            ulonglong2 r2 = *(const ulonglong2*)(wr + k);
            ulonglong2 z2 = *(const ulonglong2*)(wz + k);
            ulonglong2 n2 = *(const ulonglong2*)(wn + k);
            unsigned long long h01 = *(const unsigned long long*)(hs + ((k >> 1) << 6) + (b << 1));
            unsigned long long h23 = *(const unsigned long long*)(hs + (((k >> 1) + 1) << 6) + (b << 1));
            ffma2(ar2, r2.x, h01); ffma2(az2, z2.x, h01); ffma2(an2, n2.x, h01);
            ffma2(ar2, r2.y, h23); ffma2(az2, z2.y, h23); ffma2(an2, n2.y, h23);
        }
        float ar = f2sum(ar2), az = f2sum(az2), an = f2sum(an2);
        if (kh) { sp[0][jl][b] = ar; sp[1][jl][b] = az; sp[2][jl][b] = an; }
        __syncthreads();
        if (!kh) {
            ar += sp[0][jl][b]; az += sp[1][jl][b]; an += sp[2][jl][b];
            int row = b * Tc + t;
            float r = 1.f / (1.f + expf(-(g0 + ar + br)));
            float z = 1.f / (1.f + expf(-(g1 + az + bz)));
            float n = tanhf(g2 + r * (an + bn));
            float hold = hs[hidx(j, b)];
            float hnew = (1.f - z) * n + z * hold;
            __stcg(hout + hidx(j, b), hnew);
            if (layer == 0) {
                __nv_bfloat16 h, l; splits(hnew, h, l);
                g_hs0_hi[(long long)row * Hc + j] = h;
                g_hs0_lo[(long long)row * Hc + j] = l;
            } else {
                __half h, l; splith(hnew, h, l);
                g_cat_fh[(long long)row * H3c + j] = h;
                g_cat_fl[(long long)row * H3c + j] = l;
            }
        }
        // grid barrier (skip after the last step)
        if (t + 1 < Tc) {
            __syncthreads();
            if (tid == 0) {
                unsigned int gen;
                asm volatile("ld.global.relaxed.gpu.u32 %0, [%1];"
                             : "=r"(gen) : "l"(pgen));
                int old;
                asm volatile("atom.global.add.release.gpu.s32 %0, [%1], 1;"
                             : "=r"(old) : "l"(pctr) : "memory");
                if (old == (int)gridDim.x - 1) {
                    asm volatile("st.global.relaxed.gpu.s32 [%0], 0;"
                                 :: "l"(pctr) : "memory");
                    asm volatile("red.global.add.release.gpu.u32 [%0], 1;"
                                 :: "l"(pgen) : "memory");
                } else {
                    unsigned int g2v;
                    do {
                        asm volatile("ld.global.acquire.gpu.u32 %0, [%1];"
                                     : "=r"(g2v) : "l"(pgen) : "memory");
                    } while (g2v == gen);
                }
            }
            __syncthreads();
        }
    }
}

// ---------------- softmax (256 wide) -> attn fp16 planes ----------------
__global__ void softmax_kernel() {
    int row = blockIdx.x, tid = threadIdx.x;
    __shared__ float sm_[8], ss_[8];
    float v = g_scores[(long long)row * Sc + tid];
    float m = v;
#pragma unroll
    for (int o = 16; o; o >>= 1) m = fmaxf(m, __shfl_xor_sync(~0u, m, o));
    if ((tid & 31) == 0) sm_[tid >> 5] = m;
    __syncthreads();
    float mm = sm_[0];
#pragma unroll
    for (int i = 1; i < 8; i++) mm = fmaxf(mm, sm_[i]);
    float e = expf(v - mm);
    float s = e;
#pragma unroll
    for (int o = 16; o; o >>= 1) s += __shfl_xor_sync(~0u, s, o);
    if ((tid & 31) == 0) ss_[tid >> 5] = s;
    __syncthreads();
    float tot = 0.f;
#pragma unroll
    for (int i = 0; i < 8; i++) tot += ss_[i];
    float p = e / tot;
    __half h, l; splith(p, h, l);
    g_attn_fh[(long long)row * Sc + tid] = h;
    g_attn_fl[(long long)row * Sc + tid] = l;
}

// ======================= bf16x3 pipelined tensor GEMM (gi only) ==============
constexpr int GSTAGE = 32768;
constexpr int GSMEM  = 3 * GSTAGE;

__global__ void __launch_bounds__(256, 1)
bfx3_gemm(const __nv_bfloat16* __restrict__ Ahi, const __nv_bfloat16* __restrict__ Alo,
          const __nv_bfloat16* __restrict__ Bhi, const __nv_bfloat16* __restrict__ Blo,
          const float* __restrict__ bias, float* __restrict__ C,
          int M, int N, int K, int lda, int ldc) {
    extern __shared__ char smem[];
    uint32_t su = (uint32_t)__cvta_generic_to_shared(smem);

    const int m0 = blockIdx.x * 128, n0 = blockIdx.y * 128;
    const int tid = threadIdx.x;
    const int lane = tid & 31, wid = tid >> 5;
    const int wm = wid & 1, wn = wid >> 1;
    const int lr = lane >> 2, lc = lane & 3;

    float c[4][4][4] = {};

    auto issue_load = [&](int stage, int kt) {
        int kb = kt * 32;
        uint32_t sb = su + stage * GSTAGE;
#pragma unroll
        for (int i = 0; i < 8; i++) {
            int chunkid = tid + 256 * i;
            int plane = chunkid >> 9;
            int w = chunkid & 511;
            int r = w >> 2, cck = w & 3;
            uint32_t dst = sb + plane * 8192 + r * 64 + ((cck ^ ((r >> 1) & 3)) << 4);
            const __nv_bfloat16* src;
            if (plane < 2)
                src = (plane == 0 ? Ahi : Alo) + (long long)(m0 + r) * lda + kb + cck * 8;
            else
                src = (plane == 2 ? Bhi : Blo) + (long long)(n0 + r) * K + kb + cck * 8;
            cpa16u(dst, src);
        }
    };

    const int kt_count = K >> 5;
    issue_load(0, 0); cp_commit();
    issue_load(1, 1); cp_commit();

    for (int kt = 0; kt < kt_count; kt++) {
        if (kt + 2 < kt_count) cp_wait1(); else cp_wait0();
        __syncthreads();
        if (kt + 2 < kt_count) { issue_load((kt + 2) % 3, kt + 2); cp_commit(); }

        uint32_t sb = su + (kt % 3) * GSTAGE;
#pragma unroll
        for (int ks = 0; ks < 2; ks++) {
            uint32_t ah[4][4], al[4][4], bh[2][4], bl[2][4];
#pragma unroll
            for (int mi = 0; mi < 4; mi++) {
                int row = wm * 64 + mi * 16 + (lane & 15);
                int ch = 2 * ks + (lane >> 4);
                uint32_t a = sb + row * 64 + ((ch ^ ((row >> 1) & 3)) << 4);
                LDSM4(ah[mi], a);
                LDSM4(al[mi], a + 8192);
            }
#pragma unroll
            for (int np = 0; np < 2; np++) {
                int row = wn * 32 + np * 16 + ((lane >> 4) << 3) + (lane & 7);
                int ch = 2 * ks + ((lane >> 3) & 1);
                uint32_t a = sb + 16384 + row * 64 + ((ch ^ ((row >> 1) & 3)) << 4);
                LDSM4(bh[np], a);
                LDSM4(bl[np], a + 8192);
            }
#pragma unroll
            for (int mi = 0; mi < 4; mi++)
#pragma unroll
                for (int ni = 0; ni < 4; ni++)
                    mma16(c[mi][ni], ah[mi], &bh[ni >> 1][(ni & 1) * 2]);
#pragma unroll
            for (int mi = 0; mi < 4; mi++)
#pragma unroll
                for (int ni = 0; ni < 4; ni++)
                    mma16(c[mi][ni], ah[mi], &bl[ni >> 1][(ni & 1) * 2]);
#pragma unroll
            for (int mi = 0; mi < 4; mi++)
#pragma unroll
                for (int ni = 0; ni < 4; ni++)
                    mma16(c[mi][ni], al[mi], &bh[ni >> 1][(ni & 1) * 2]);
        }
        __syncthreads();
    }

#pragma unroll
    for (int mi = 0; mi < 4; mi++) {
#pragma unroll
        for (int ni = 0; ni < 4; ni++) {
            int row = m0 + wm * 64 + mi * 16 + lr;
            int col = n0 + wn * 32 + ni * 8 + lc * 2;
            float b0 = bias[col], b1 = bias[col + 1];
            *(float2*)(C + (long long)row * ldc + col) =
                make_float2(c[mi][ni][0] + b0, c[mi][ni][1] + b1);
            *(float2*)(C + (long long)(row + 8) * ldc + col) =
                make_float2(c[mi][ni][2] + b0, c[mi][ni][3] + b1);
        }
    }
}

// ============ fp16 pipelined GEMM: C = (sum A-terms) @ Bf^T (+bias) ============
constexpr int FPL = 8192;

template <int AT, int OUT, bool RELU, bool GUARD>
__global__ void __launch_bounds__(256, 2)
fph_gemm(const __half* __restrict__ Ahi, const __half* __restrict__ Alo,
         const __half* __restrict__ Bf, const float* __restrict__ bias,
         float* __restrict__ C, __half* __restrict__ Ch, __half* __restrict__ Cl,
         int M, int N, int K, int lda, int ldc,
         long long sA, long long sB, long long sC) {
    extern __shared__ char smem[];
    uint32_t su = (uint32_t)__cvta_generic_to_shared(smem);
    constexpr int NPL = AT + 1;
    constexpr int STG = NPL * FPL;

    Ahi += (long long)blockIdx.z * sA;
    if (AT == 2) Alo += (long long)blockIdx.z * sA;
    Bf += (long long)blockIdx.z * sB;

    const int m0 = blockIdx.x * 128, n0 = blockIdx.y * 128;
    const int tid = threadIdx.x;
    const int lane = tid & 31, wid = tid >> 5;
    const int wm = wid & 1, wn = wid >> 1;
    const int lr = lane >> 2, lc = lane & 3;

    float c[4][4][4] = {};

    auto issue_load = [&](int stage, int kt) {
        int kb = kt * 32;
        uint32_t sb = su + stage * STG;
#pragma unroll
        for (int i = 0; i < NPL * 2; i++) {
            int chunkid = tid + 256 * i;
            int plane = chunkid >> 9;
            int w = chunkid & 511;
            int r = w >> 2, cck = w & 3;
            uint32_t dst = sb + plane * FPL + r * 64 + ((cck ^ ((r >> 1) & 3)) << 4);
            const __half* src;
            bool ok = true;
            if (plane < AT) {
                src = (plane == 0 ? Ahi : Alo) + (long long)(m0 + r) * lda + kb + cck * 8;
                if (GUARD) ok = (m0 + r) < M;
            } else {
                src = Bf + (long long)(n0 + r) * K + kb + cck * 8;
            }
            if (GUARD) cpa16(dst, src, ok); else cpa16u(dst, src);
        }
    };

    const int kt_count = K >> 5;
    issue_load(0, 0); cp_commit();
    issue_load(1, 1); cp_commit();

    for (int kt = 0; kt < kt_count; kt++) {
        if (kt + 2 < kt_count) cp_wait1(); else cp_wait0();
        __syncthreads();
        if (kt + 2 < kt_count) { issue_load((kt + 2) % 3, kt + 2); cp_commit(); }

        uint32_t sb = su + (kt % 3) * STG;
#pragma unroll
        for (int ks = 0; ks < 2; ks++) {
            uint32_t ah[AT][4][4], bh[2][4];
#pragma unroll
            for (int t = 0; t < AT; t++)
#pragma unroll
                for (int mi = 0; mi < 4; mi++) {
                    int row = wm * 64 + mi * 16 + (lane & 15);
                    int ch = 2 * ks + (lane >> 4);
                    uint32_t a = sb + t * FPL + row * 64 + ((ch ^ ((row >> 1) & 3)) << 4);
                    LDSM4(ah[t][mi], a);
                }
#pragma unroll
            for (int np = 0; np < 2; np++) {
                int row = wn * 32 + np * 16 + ((lane >> 4) << 3) + (lane & 7);
                int ch = 2 * ks + ((lane >> 3) & 1);
                uint32_t a = sb + AT * FPL + row * 64 + ((ch ^ ((row >> 1) & 3)) << 4);
                LDSM4(bh[np], a);
            }
#pragma unroll
            for (int t = 0; t < AT; t++)
#pragma unroll
                for (int mi = 0; mi < 4; mi++)
#pragma unroll
                    for (int ni = 0; ni < 4; ni++)
                        mma16h(c[mi][ni], ah[t][mi], &bh[ni >> 1][(ni & 1) * 2]);
        }
        __syncthreads();
    }

#pragma unroll
    for (int mi = 0; mi < 4; mi++) {
#pragma unroll
        for (int ni = 0; ni < 4; ni++) {
            int row = m0 + wm * 64 + mi * 16 + lr;
            int col = n0 + wn * 32 + ni * 8 + lc * 2;
            float b0 = bias ? bias[col] : 0.f;
            float b1 = bias ? bias[col + 1] : 0.f;
            float v0 = c[mi][ni][0] + b0, v1 = c[mi][ni][1] + b1;
            float v2 = c[mi][ni][2] + b0, v3 = c[mi][ni][3] + b1;
            if (RELU) {
                v0 = fmaxf(v0, 0.f); v1 = fmaxf(v1, 0.f);
                v2 = fmaxf(v2, 0.f); v3 = fmaxf(v3, 0.f);
            }
            bool ok0 = !GUARD || row < M;
            bool ok1 = !GUARD || (row + 8) < M;
            if (OUT == 0) {
                float* Cz = C + (long long)blockIdx.z * sC;
                if (ok0)
                    *(float2*)(Cz + (long long)row * ldc + col) = make_float2(v0, v1);
                if (ok1)
                    *(float2*)(Cz + (long long)(row + 8) * ldc + col) = make_float2(v2, v3);
            } else if (OUT == 1) {
                __half* Co = Ch + (long long)blockIdx.z * sC;
                if (ok0)
                    *(__half2*)(Co + (long long)row * ldc + col) = __floats2half2_rn(v0, v1);
                if (ok1)
                    *(__half2*)(Co + (long long)(row + 8) * ldc + col) = __floats2half2_rn(v2, v3);
            } else {
                __half* Coh = Ch + (long long)blockIdx.z * sC;
                __half* Col = Cl + (long long)blockIdx.z * sC;
                if (ok0) {
                    __half2 h = __floats2half2_rn(v0, v1);
                    __half2 l = __floats2half2_rn(v0 - __half2float(__low2half(h)),
                                                  v1 - __half2float(__high2half(h)));
                    *(__half2*)(Coh + (long long)row * ldc + col) = h;
                    *(__half2*)(Col + (long long)row * ldc + col) = l;
                }
                if (ok1) {
                    __half2 h = __floats2half2_rn(v2, v3);
                    __half2 l = __floats2half2_rn(v2 - __half2float(__low2half(h)),
                                                  v3 - __half2float(__high2half(h)));
                    *(__half2*)(Coh + (long long)(row + 8) * ldc + col) = h;
                    *(__half2*)(Col + (long long)(row + 8) * ldc + col) = l;
                }
            }
        }
    }
}

// ---------------- host launch ----------------
extern "C" void kernel_launch(void* const* d_in, const int* in_sizes, int n_in,
                              void* d_out, int out_size) {
    (void)in_sizes; (void)n_in; (void)out_size;
    const float* enc    = (const float*)d_in[0];
    const float* ehid   = (const float*)d_in[1];
    const int*   words  = (const int*)d_in[2];
    const float* embed  = (const float*)d_in[3];
    const float* Wih0   = (const float*)d_in[4];
    const float* Whh0   = (const float*)d_in[5];
    const float* bih0   = (const float*)d_in[6];
    const float* bhh0   = (const float*)d_in[7];
    const float* Wih1   = (const float*)d_in[8];
    const float* Whh1   = (const float*)d_in[9];
    const float* bih1   = (const float*)d_in[10];
    const float* bhh1   = (const float*)d_in[11];
    const float* attn_W = (const float*)d_in[12];
    const float* attn_b = (const float*)d_in[13];
    const float* aw_W   = (const float*)d_in[14];
    const float* aw_b   = (const float*)d_in[15];
    const float* out_W  = (const float*)d_in[16];
    const float* out_b  = (const float*)d_in[17];
    float* out = (float*)d_out;

    float *p_gi, *p_sc;
    cudaGetSymbolAddress((void**)&p_gi, g_gi);
    cudaGetSymbolAddress((void**)&p_sc, g_scores);

#define GETP(sym) \
    __nv_bfloat16 *sym##_h, *sym##_l; \
    cudaGetSymbolAddress((void**)&sym##_h, sym##_hi); \
    cudaGetSymbolAddress((void**)&sym##_l, sym##_lo);
    GETP(g_x) GETP(g_wih0) GETP(g_wih1) GETP(g_hs0)
#undef GETP
    __half *p_encfh, *p_encfl, *p_awnf, *p_projf, *p_encTf;
    __half *p_attnfh, *p_attnfl, *p_catfh, *p_catfl, *p_awWf, *p_of, *p_wf;
    cudaGetSymbolAddress((void**)&p_encfh,  g_enc_fh);
    cudaGetSymbolAddress((void**)&p_encfl,  g_enc_fl);
    cudaGetSymbolAddress((void**)&p_awnf,   g_attnW_f);
    cudaGetSymbolAddress((void**)&p_projf,  g_proj_f);
    cudaGetSymbolAddress((void**)&p_encTf,  g_encT_f);
    cudaGetSymbolAddress((void**)&p_attnfh, g_attn_fh);
    cudaGetSymbolAddress((void**)&p_attnfl, g_attn_fl);
    cudaGetSymbolAddress((void**)&p_catfh,  g_cat_fh);
    cudaGetSymbolAddress((void**)&p_catfl,  g_cat_fl);
    cudaGetSymbolAddress((void**)&p_awWf,   g_awW_f);
    cudaGetSymbolAddress((void**)&p_of,     g_o_f);
    cudaGetSymbolAddress((void**)&p_wf,     g_outW_f);

    cudaFuncSetAttribute(bfx3_gemm,
                         cudaFuncAttributeMaxDynamicSharedMemorySize, GSMEM);
    cudaFuncSetAttribute((fph_gemm<2, 1, false, false>),
                         cudaFuncAttributeMaxDynamicSharedMemorySize, 3 * 3 * FPL);
    cudaFuncSetAttribute((fph_gemm<2, 0, false, true>),
                         cudaFuncAttributeMaxDynamicSharedMemorySize, 3 * 3 * FPL);
    cudaFuncSetAttribute((fph_gemm<2, 2, false, true>),
                         cudaFuncAttributeMaxDynamicSharedMemorySize, 3 * 3 * FPL);
    cudaFuncSetAttribute((fph_gemm<2, 1, true, false>),
                         cudaFuncAttributeMaxDynamicSharedMemorySize, 3 * 3 * FPL);
    cudaFuncSetAttribute((fph_gemm<1, 0, false, false>),
                         cudaFuncAttributeMaxDynamicSharedMemorySize, 3 * 2 * FPL);
    cudaFuncSetAttribute(gru_layer_kernel,
                         cudaFuncAttributeMaxDynamicSharedMemorySize, 90112);

    // ---- streams/events (frozen round-10 structure) ----
    static cudaStream_t s1 = nullptr, s2 = nullptr;
    static cudaEvent_t e0 = nullptr, e_aw = nullptr, e_outw = nullptr, e_proj = nullptr;
    if (!s1) {
        cudaStreamCreateWithFlags(&s1, cudaStreamNonBlocking);
        cudaStreamCreateWithFlags(&s2, cudaStreamNonBlocking);
        cudaEventCreateWithFlags(&e0,     cudaEventDisableTiming);
        cudaEventCreateWithFlags(&e_aw,   cudaEventDisableTiming);
        cudaEventCreateWithFlags(&e_outw, cudaEventDisableTiming);
        cudaEventCreateWithFlags(&e_proj, cudaEventDisableTiming);
    }

    // fork
    cudaEventRecord(e0, 0);
    cudaStreamWaitEvent(s1, e0, 0);
    cudaStreamWaitEvent(s2, e0, 0);

    // ---- s1: weight conversions for the output head ----
    {
        int n4 = H3c * H3c / 4;
        split_half_kernel<<<(n4 + 255) / 256, 256, 0, s1>>>(aw_W, p_awWf, n4);
        cudaEventRecord(e_aw, s1);
        n4 = Vc * H3c / 4;
        split_half_kernel<<<(n4 + 255) / 256, 256, 0, s1>>>(out_W, p_wf, n4);
        cudaEventRecord(e_outw, s1);
    }

    // ---- s2: attention prep + proj GEMM ----
    {
        int n4 = Bc * Sc * 2 * Hc / 4;
        split_half2_kernel<<<(n4 + 255) / 256, 256, 0, s2>>>(enc, p_encfh, p_encfl, n4);
        n4 = Hc * 2 * Hc / 4;
        split_half_kernel<<<(n4 + 255) / 256, 256, 0, s2>>>(attn_W, p_awnf, n4);
        transpose_enc<<<dim3(32, 8, 32), dim3(32, 8), 0, s2>>>(enc);
        fph_gemm<2, 1, false, false><<<dim3(64, 4), 256, 3 * 3 * FPL, s2>>>(
            p_encfh, p_encfl, p_awnf, attn_b, nullptr, p_projf, nullptr,
            Bc * Sc, Hc, 2 * Hc, 2 * Hc, Hc, 0, 0, 0);
        cudaEventRecord(e_proj, s2);
    }

    // ---- main stream: GRU critical path ----
    {
        int tot = H3c * EP;
        split_pad_kernel<<<(tot + 255) / 256, 256>>>(Wih0, g_wih0_h, g_wih0_l,
                                                     H3c, Ec, EP);
        int n4 = H3c * Hc / 4;
        split_kernel<<<(n4 + 255) / 256, 256>>>(Wih1, g_wih1_h, g_wih1_l, n4);
    }
    embed_relu_kernel<<<ROWS, 128>>>(words, embed);

    h0t_kernel<<<64, 256>>>(ehid, 0);
    bfx3_gemm<<<dim3(16, 12), 256, GSMEM>>>(
        g_x_h, g_x_l, g_wih0_h, g_wih0_l, bih0, p_gi,
        ROWS, H3c, EP, EP, H3c);
    gru_layer_kernel<<<128, 256, 90112>>>(Whh0, bhh0, 0);

    h0t_kernel<<<64, 256>>>(ehid, 1);
    bfx3_gemm<<<dim3(16, 12), 256, GSMEM>>>(
        g_hs0_h, g_hs0_l, g_wih1_h, g_wih1_l, bih1, p_gi,
        ROWS, H3c, Hc, Hc, H3c);
    gru_layer_kernel<<<128, 256, 90112>>>(Whh1, bhh1, 1);

    // ---- join: attention ----
    cudaStreamWaitEvent(0, e_proj, 0);
    fph_gemm<2, 0, false, true><<<dim3(1, 2, 32), 256, 3 * 3 * FPL>>>(
        p_catfh, p_catfl, p_projf, nullptr, p_sc, nullptr, nullptr,
        Tc, Sc, Hc, H3c, Sc,
        (long long)Tc * H3c, (long long)Sc * Hc, (long long)Tc * Sc);
    softmax_kernel<<<ROWS, 256>>>();
    fph_gemm<2, 2, false, true><<<dim3(1, 8, 32), 256, 3 * 3 * FPL>>>(
        p_attnfh, p_attnfl, p_encTf, nullptr, nullptr,
        p_catfh + Hc, p_catfl + Hc,
        Tc, 2 * Hc, Sc, Sc, H3c,
        (long long)Tc * Sc, (long long)2 * Hc * Sc, (long long)Tc * H3c);

    // ---- output head ----
    cudaStreamWaitEvent(0, e_aw, 0);
    fph_gemm<2, 1, true, false><<<dim3(16, 12), 256, 3 * 3 * FPL>>>(
        p_catfh, p_catfl, p_awWf, aw_b, nullptr, p_of, nullptr,
        ROWS, H3c, H3c, H3c, H3c, 0, 0, 0);

    cudaStreamWaitEvent(0, e_outw, 0);
    fph_gemm<1, 0, false, false><<<dim3(16, 250), 256, 3 * 2 * FPL>>>(
        p_of, nullptr, p_wf, out_b, out, nullptr, nullptr,
        ROWS, Vc, H3c, H3c, Vc, 0, 0, 0);
}